// round 1
// baseline (speedup 1.0000x reference)
#include <cuda_runtime.h>
#include <cstdint>
#include <cstdio>

#define Bb   2
#define Ss   2048
#define Dd   2048
#define Hh   32
#define HDd  64
#define MBb  16
#define Nsteps 128
#define EPSf 1e-5f

// ---------------- scratch (static device arrays; no allocation) ----------------
__device__ float g_q[Bb*Ss*Dd];     // q after proj (+rope); reused as post-LN buffer at the end
__device__ float g_k[Bb*Ss*Dd];
__device__ float g_v[Bb*Ss*Dd];
__device__ float g_y[Bb*Ss*Dd];     // scan output (pre final LN)
__device__ float g_lr[Bb*Ss*Hh];    // sigmoid(ilr)/HD per (token, head)

// ---------------- packed f32x2 helpers (Blackwell FFMA2 path) ----------------
__device__ __forceinline__ unsigned long long pack2f(float lo, float hi){
    unsigned long long r;
    asm("mov.b64 %0, {%1, %2};" : "=l"(r) : "f"(lo), "f"(hi));
    return r;
}
__device__ __forceinline__ unsigned long long ffma2(unsigned long long a,
                                                    unsigned long long b,
                                                    unsigned long long c){
    unsigned long long d;
    asm("fma.rn.f32x2 %0, %1, %2, %3;" : "=l"(d) : "l"(a), "l"(b), "l"(c));
    return d;
}
__device__ __forceinline__ void unpack2f(unsigned long long v, float& lo, float& hi){
    asm("mov.b64 {%0, %1}, %2;" : "=f"(lo), "=f"(hi) : "l"(v));
}

// ---------------- NT GEMM: C[m,n] = sum_k A[m,k] * Bw[n,k] ----------------
// 128x128 block tile, K-tile 16, 256 threads, 8x8 per-thread, f32x2 FMA.
__global__ __launch_bounds__(256, 2)
void gemm_nt(const float* __restrict__ A, const float* __restrict__ Bw,
             float* __restrict__ C, int M, int Ncols, int K)
{
    __shared__ float As[16][132];
    __shared__ float Bs[16][132];
    const int tid = threadIdx.x;
    const int tx = tid & 15, ty = tid >> 4;
    const int bm = blockIdx.y * 128, bn = blockIdx.x * 128;

    unsigned long long acc[8][4];
    #pragma unroll
    for (int i = 0; i < 8; i++)
        #pragma unroll
        for (int j = 0; j < 4; j++) acc[i][j] = 0ULL;

    const int lrow = tid >> 2;       // 0..63
    const int lk   = (tid & 3) * 4;  // 0,4,8,12

    for (int k0 = 0; k0 < K; k0 += 16) {
        #pragma unroll
        for (int p = 0; p < 2; p++){
            int r = lrow + p * 64;
            float4 va = *reinterpret_cast<const float4*>(A  + (size_t)(bm + r) * K + k0 + lk);
            float4 vb = *reinterpret_cast<const float4*>(Bw + (size_t)(bn + r) * K + k0 + lk);
            As[lk+0][r] = va.x; As[lk+1][r] = va.y; As[lk+2][r] = va.z; As[lk+3][r] = va.w;
            Bs[lk+0][r] = vb.x; Bs[lk+1][r] = vb.y; Bs[lk+2][r] = vb.z; Bs[lk+3][r] = vb.w;
        }
        __syncthreads();
        #pragma unroll
        for (int kk = 0; kk < 16; kk++){
            float a[8];
            float4 a0 = *reinterpret_cast<const float4*>(&As[kk][ty*8]);
            float4 a1 = *reinterpret_cast<const float4*>(&As[kk][ty*8+4]);
            a[0]=a0.x; a[1]=a0.y; a[2]=a0.z; a[3]=a0.w;
            a[4]=a1.x; a[5]=a1.y; a[6]=a1.z; a[7]=a1.w;
            float4 b0 = *reinterpret_cast<const float4*>(&Bs[kk][tx*8]);
            float4 b1 = *reinterpret_cast<const float4*>(&Bs[kk][tx*8+4]);
            unsigned long long b2[4];
            b2[0] = pack2f(b0.x, b0.y); b2[1] = pack2f(b0.z, b0.w);
            b2[2] = pack2f(b1.x, b1.y); b2[3] = pack2f(b1.z, b1.w);
            #pragma unroll
            for (int i = 0; i < 8; i++){
                unsigned long long a2 = pack2f(a[i], a[i]);
                #pragma unroll
                for (int j = 0; j < 4; j++) acc[i][j] = ffma2(a2, b2[j], acc[i][j]);
            }
        }
        __syncthreads();
    }
    #pragma unroll
    for (int i = 0; i < 8; i++){
        float* crow = C + (size_t)(bm + ty*8 + i) * Ncols + bn + tx*8;
        #pragma unroll
        for (int j = 0; j < 4; j++){
            float lo, hi; unpack2f(acc[i][j], lo, hi);
            crow[2*j] = lo; crow[2*j+1] = hi;
        }
    }
}

// ---------------- RoPE in place on q,k,v ----------------
__global__ void rope_kernel(const float* __restrict__ pf)
{
    int idx = blockIdx.x * blockDim.x + threadIdx.x;
    const int total = Bb * Ss * Hh * (HDd/2);
    if (idx >= total) return;
    int p   = idx & 31;
    int h   = (idx >> 5) & 31;
    int tok = idx >> 10;              // b*S + s
    int s   = tok & (Ss - 1);
    float f = pf[s*32 + p];
    float sn, c;
    sincosf(f, &sn, &c);
    size_t off = (size_t)tok * Dd + h * HDd + 2 * p;
    float2* q2 = reinterpret_cast<float2*>(g_q + off);
    float2* k2 = reinterpret_cast<float2*>(g_k + off);
    float2* v2 = reinterpret_cast<float2*>(g_v + off);
    float2 a;
    a = *q2; *q2 = make_float2(a.x*c - a.y*sn, a.x*sn + a.y*c);
    a = *k2; *k2 = make_float2(a.x*c - a.y*sn, a.x*sn + a.y*c);
    a = *v2; *v2 = make_float2(a.x*c - a.y*sn, a.x*sn + a.y*c);
}

// ---------------- per-(token, head) learning-rate scalar ----------------
__global__ __launch_bounds__(256)
void lr_kernel(const float* __restrict__ x, const float* __restrict__ ilrW,
               const float* __restrict__ ilrb)
{
    __shared__ float xs[Dd];
    int row = blockIdx.x;                 // token index in [0, B*S)
    for (int i = threadIdx.x; i < Dd; i += 256) xs[i] = x[(size_t)row * Dd + i];
    __syncthreads();
    int w = threadIdx.x >> 5, lane = threadIdx.x & 31;
    for (int h = w; h < Hh; h += 8){
        const float* wr = ilrW + (size_t)h * Dd;
        float s = 0.f;
        for (int m = lane; m < Dd; m += 32) s = fmaf(xs[m], wr[m], s);
        #pragma unroll
        for (int o = 16; o; o >>= 1) s += __shfl_xor_sync(0xffffffffu, s, o);
        if (lane == 0){
            float t = s + ilrb[h];
            g_lr[(size_t)row * Hh + h] = (1.0f / (1.0f + expf(-t))) * (1.0f / (float)HDd);
        }
    }
}

// ---------------- sequential TTT scan: 1 block per (b,h) ----------------
#define SR 65
__global__ __launch_bounds__(512, 1)
void scan_kernel(const float* __restrict__ lgs, const float* __restrict__ tg,
                 const float* __restrict__ tb,  const float* __restrict__ W0,
                 const float* __restrict__ b0)
{
    __shared__ float Wm[64*64];
    __shared__ float XQ[16*SR], XK[16*SR], XV[16*SR];
    __shared__ float Zs[16*SR], ZQ[16*SR], Gr[16*SR];
    __shared__ float bb[64], bnew[64], gv[64], bev[64];
    __shared__ float Attn[16][16], Cc[16][17];
    __shared__ float lrv[16], gsv[16];

    const int bh = blockIdx.x;
    const int b = bh >> 5, h = bh & 31;
    const int tid = threadIdx.x, w = tid >> 5, lane = tid & 31;

    for (int i = tid; i < 4096; i += 512) Wm[i] = W0[h*4096 + i];
    if (tid < 64){ bb[tid] = b0[h*64 + tid]; gv[tid] = tg[h*64 + tid]; bev[tid] = tb[h*64 + tid]; }
    if (tid < 16) gsv[tid] = fmaxf(1.0f / (float)(tid + 1) + lgs[tid], 0.0f);
    __syncthreads();

    const size_t base = (size_t)b * Ss * Dd + h * HDd;

    for (int n = 0; n < Nsteps; n++){
        // ---- load minibatch tiles ----
        for (int i = tid; i < 16*64; i += 512){
            int r = i >> 6, c = i & 63;
            size_t gi = base + (size_t)(n*MBb + r) * Dd + c;
            XQ[r*SR + c] = g_q[gi];
            XK[r*SR + c] = g_k[gi];
            XV[r*SR + c] = g_v[gi];
        }
        if (tid < 16) lrv[tid] = g_lr[((size_t)b * Ss + n*MBb + tid) * Hh + h];
        __syncthreads();

        // ---- phase 2: Z = XK@W + bb, ZQ = XQ@W, Attn = tril(XQ@XK^T) ----
        {
            const int i = w;
            float z0 = bb[lane], z1 = bb[lane+32], p0 = 0.f, p1 = 0.f;
            #pragma unroll 8
            for (int kk = 0; kk < 64; kk++){
                float w0 = Wm[kk*64 + lane], w1 = Wm[kk*64 + lane + 32];
                float xk = XK[i*SR + kk], xq = XQ[i*SR + kk];
                z0 = fmaf(xk, w0, z0); z1 = fmaf(xk, w1, z1);
                p0 = fmaf(xq, w0, p0); p1 = fmaf(xq, w1, p1);
            }
            Zs[i*SR + lane] = z0; Zs[i*SR + lane + 32] = z1;
            ZQ[i*SR + lane] = p0; ZQ[i*SR + lane + 32] = p1;
            if (lane < 16){
                float s = 0.f;
                #pragma unroll 8
                for (int kk = 0; kk < 64; kk++) s = fmaf(XQ[i*SR + kk], XK[lane*SR + kk], s);
                Attn[i][lane] = s;
            }
        }
        __syncthreads();

        // ---- phase 3: grad = ln_l2_bwd(Z, XV - XK); Cc coefficients ----
        {
            const int i = w;
            float z0 = Zs[i*SR + lane], z1 = Zs[i*SR + lane + 32];
            float s = z0 + z1;
            #pragma unroll
            for (int o = 16; o; o >>= 1) s += __shfl_xor_sync(0xffffffffu, s, o);
            float mu = s * (1.0f/64.0f);
            float d0 = z0 - mu, d1 = z1 - mu;
            float vs = d0*d0 + d1*d1;
            #pragma unroll
            for (int o = 16; o; o >>= 1) vs += __shfl_xor_sync(0xffffffffu, vs, o);
            float rstd = rsqrtf(vs * (1.0f/64.0f) + EPSf);
            float zh0 = d0 * rstd, zh1 = d1 * rstd;
            float g0 = gv[lane], g1 = gv[lane+32];
            float dy0 = fmaf(g0, zh0, bev[lane])    - (XV[i*SR + lane]    - XK[i*SR + lane]);
            float dy1 = fmaf(g1, zh1, bev[lane+32]) - (XV[i*SR + lane+32] - XK[i*SR + lane+32]);
            float dz0 = dy0 * g0, dz1 = dy1 * g1;
            float m1 = dz0 + dz1;
            float m2 = fmaf(dz0, zh0, dz1*zh1);
            #pragma unroll
            for (int o = 16; o; o >>= 1){
                m1 += __shfl_xor_sync(0xffffffffu, m1, o);
                m2 += __shfl_xor_sync(0xffffffffu, m2, o);
            }
            m1 *= (1.0f/64.0f); m2 *= (1.0f/64.0f);
            Gr[i*SR + lane]      = (dz0 - m1 - zh0*m2) * rstd;
            Gr[i*SR + lane + 32] = (dz1 - m1 - zh1*m2) * rstd;
        }
        if (tid < 256){
            int i = tid >> 4, j = tid & 15;
            Cc[i][j] = (j <= i) ? gsv[i] * lrv[j] * (Attn[i][j] + 1.0f) : 0.0f;
        }
        __syncthreads();

        // ---- phase 4: Z_bar + ln_fwd + y; W update; b update ----
        {
            const int i = w;
            float zb0 = ZQ[i*SR + lane]      + bb[lane];
            float zb1 = ZQ[i*SR + lane + 32] + bb[lane + 32];
            for (int j = 0; j <= i; j++){
                float c = Cc[i][j];
                zb0 = fmaf(-c, Gr[j*SR + lane],      zb0);
                zb1 = fmaf(-c, Gr[j*SR + lane + 32], zb1);
            }
            float s = zb0 + zb1;
            #pragma unroll
            for (int o = 16; o; o >>= 1) s += __shfl_xor_sync(0xffffffffu, s, o);
            float mu = s * (1.0f/64.0f);
            float d0 = zb0 - mu, d1 = zb1 - mu;
            float vs = d0*d0 + d1*d1;
            #pragma unroll
            for (int o = 16; o; o >>= 1) vs += __shfl_xor_sync(0xffffffffu, vs, o);
            float rstd = rsqrtf(vs * (1.0f/64.0f) + EPSf);
            size_t go = base + (size_t)(n*MBb + i) * Dd;
            g_y[go + lane]      = XQ[i*SR + lane]      + fmaf(gv[lane]      * d0, rstd, bev[lane]);
            g_y[go + lane + 32] = XQ[i*SR + lane + 32] + fmaf(gv[lane + 32] * d1, rstd, bev[lane + 32]);
        }
        {
            float le = gsv[15];
            #pragma unroll
            for (int q2 = 0; q2 < 4; q2++){
                int kr = w*4 + q2;
                float a0 = 0.f, a1 = 0.f;
                #pragma unroll
                for (int j = 0; j < 16; j++){
                    float t = le * lrv[j] * XK[j*SR + kr];
                    a0 = fmaf(t, Gr[j*SR + lane],      a0);
                    a1 = fmaf(t, Gr[j*SR + lane + 32], a1);
                }
                Wm[kr*64 + lane]      -= a0;
                Wm[kr*64 + lane + 32] -= a1;
            }
            if (tid < 64){
                float a = 0.f;
                #pragma unroll
                for (int j = 0; j < 16; j++) a = fmaf(le * lrv[j], Gr[j*SR + tid], a);
                bnew[tid] = bb[tid] - a;
            }
        }
        __syncthreads();
        if (tid < 64) bb[tid] = bnew[tid];
        __syncthreads();
    }
}

// ---------------- final layernorm over D ----------------
__global__ __launch_bounds__(256)
void postln_kernel(const float* __restrict__ yin, const float* __restrict__ gmm,
                   const float* __restrict__ bta, float* __restrict__ outp)
{
    __shared__ float red[8];
    int row = blockIdx.x, tid = threadIdx.x;
    const float* r = yin + (size_t)row * Dd;
    float vals[8];
    float s = 0.f;
    #pragma unroll
    for (int i = 0; i < 8; i++){ vals[i] = r[tid + 256*i]; s += vals[i]; }
    #pragma unroll
    for (int o = 16; o; o >>= 1) s += __shfl_xor_sync(0xffffffffu, s, o);
    if ((tid & 31) == 0) red[tid >> 5] = s;
    __syncthreads();
    float tot = 0.f;
    #pragma unroll
    for (int i = 0; i < 8; i++) tot += red[i];
    float mu = tot * (1.0f / (float)Dd);
    __syncthreads();
    float vs = 0.f;
    #pragma unroll
    for (int i = 0; i < 8; i++){ float d = vals[i] - mu; vs = fmaf(d, d, vs); }
    #pragma unroll
    for (int o = 16; o; o >>= 1) vs += __shfl_xor_sync(0xffffffffu, vs, o);
    if ((tid & 31) == 0) red[tid >> 5] = vs;
    __syncthreads();
    float vtot = 0.f;
    #pragma unroll
    for (int i = 0; i < 8; i++) vtot += red[i];
    float rstd = rsqrtf(vtot * (1.0f / (float)Dd) + EPSf);
    float* orow = outp + (size_t)row * Dd;
    #pragma unroll
    for (int i = 0; i < 8; i++){
        int c = tid + 256*i;
        orow[c] = fmaf(gmm[c] * (vals[i] - mu), rstd, bta[c]);
    }
}

// ---------------- launch ----------------
extern "C" void kernel_launch(void* const* d_in, const int* in_sizes, int n_in,
                              void* d_out, int out_size)
{
    const float* x    = (const float*)d_in[0];
    const float* pf   = (const float*)d_in[1];
    const float* Wq   = (const float*)d_in[2];
    const float* Wk   = (const float*)d_in[3];
    const float* Wv   = (const float*)d_in[4];
    const float* Wo   = (const float*)d_in[5];
    const float* pg   = (const float*)d_in[6];
    const float* pb   = (const float*)d_in[7];
    const float* ilrW = (const float*)d_in[8];
    const float* ilrb = (const float*)d_in[9];
    const float* lgs  = (const float*)d_in[10];
    const float* tg   = (const float*)d_in[11];
    const float* tb   = (const float*)d_in[12];
    const float* W0   = (const float*)d_in[13];
    const float* b0   = (const float*)d_in[14];
    float* outp = (float*)d_out;

    float *qp, *kp, *vp, *yp;
    cudaGetSymbolAddress((void**)&qp, g_q);
    cudaGetSymbolAddress((void**)&kp, g_k);
    cudaGetSymbolAddress((void**)&vp, g_v);
    cudaGetSymbolAddress((void**)&yp, g_y);

    const int M = Bb * Ss;          // 4096
    dim3 ggrid(Dd / 128, M / 128);  // (16, 32)

    gemm_nt<<<ggrid, 256>>>(x, Wq, qp, M, Dd, Dd);
    gemm_nt<<<ggrid, 256>>>(x, Wk, kp, M, Dd, Dd);
    gemm_nt<<<ggrid, 256>>>(x, Wv, vp, M, Dd, Dd);

    const int rope_total = Bb * Ss * Hh * (HDd/2);
    rope_kernel<<<(rope_total + 255) / 256, 256>>>(pf);

    lr_kernel<<<M, 256>>>(x, ilrW, ilrb);

    scan_kernel<<<Bb * Hh, 512>>>(lgs, tg, tb, W0, b0);

    // reuse g_q as the post-LN buffer (q no longer needed)
    postln_kernel<<<M, 256>>>(yp, pg, pb, qp);

    gemm_nt<<<ggrid, 256>>>(qp, Wo, outp, M, Dd, Dd);
}

// round 3
// speedup vs baseline: 1.7573x; 1.7573x over previous
#include <cuda_runtime.h>
#include <cuda_fp16.h>
#include <cstdint>
#include <cstdio>

#define Bb   2
#define Ss   2048
#define Dd   2048
#define Hh   32
#define HDd  64
#define MBb  16
#define Nsteps 128
#define EPSf 1e-5f

// ---------------- scratch (static device arrays; no allocation) ----------------
__device__ float  g_q[Bb*Ss*Dd];
__device__ float  g_k[Bb*Ss*Dd];
__device__ float  g_v[Bb*Ss*Dd];
__device__ float  g_y[Bb*Ss*Dd];
__device__ float  g_lr[Bb*Ss*Hh];
__device__ __half g_xh[Bb*Ss*Dd];     // hi fp16 split of GEMM A operand
__device__ __half g_xl[Bb*Ss*Dd];     // lo fp16 split
__device__ __half g_wh[3*Dd*Dd];      // hi split of up to 3 weight matrices
__device__ __half g_wl[3*Dd*Dd];

// ---------------- PTX helpers ----------------
__device__ __forceinline__ uint32_t smem_u32(const void* p){
    uint32_t a;
    asm("{ .reg .u64 t; cvta.to.shared.u64 t, %1; cvt.u32.u64 %0, t; }" : "=r"(a) : "l"(p));
    return a;
}
__device__ __forceinline__ void cpasync16(uint32_t s, const void* g){
    asm volatile("cp.async.cg.shared.global [%0], [%1], 16;" :: "r"(s), "l"(g) : "memory");
}
#define CP_COMMIT() asm volatile("cp.async.commit_group;" ::: "memory")
#define CP_WAIT(n)  asm volatile("cp.async.wait_group %0;" :: "n"(n) : "memory")

__device__ __forceinline__ void ldsm4(uint32_t* r, uint32_t a){
    asm volatile("ldmatrix.sync.aligned.m8n8.x4.shared.b16 {%0,%1,%2,%3}, [%4];"
        : "=r"(r[0]), "=r"(r[1]), "=r"(r[2]), "=r"(r[3]) : "r"(a));
}
__device__ __forceinline__ void mma16816(float* d, const uint32_t* a, const uint32_t* b){
    asm volatile("mma.sync.aligned.m16n8k16.row.col.f32.f16.f16.f32 "
        "{%0,%1,%2,%3}, {%4,%5,%6,%7}, {%8,%9}, {%0,%1,%2,%3};"
        : "+f"(d[0]), "+f"(d[1]), "+f"(d[2]), "+f"(d[3])
        : "r"(a[0]), "r"(a[1]), "r"(a[2]), "r"(a[3]), "r"(b[0]), "r"(b[1]));
}

// ---------------- fp16 hi/lo split kernel ----------------
__global__ __launch_bounds__(256)
void split_kernel(const float* __restrict__ src, __half* __restrict__ hi,
                  __half* __restrict__ lo, int n4)
{
    int i = blockIdx.x * blockDim.x + threadIdx.x;
    if (i >= n4) return;
    float4 v = reinterpret_cast<const float4*>(src)[i];
    __half h0 = __float2half_rn(v.x), h1 = __float2half_rn(v.y);
    __half h2 = __float2half_rn(v.z), h3 = __float2half_rn(v.w);
    __half l0 = __float2half_rn(v.x - __half2float(h0));
    __half l1 = __float2half_rn(v.y - __half2float(h1));
    __half l2 = __float2half_rn(v.z - __half2float(h2));
    __half l3 = __float2half_rn(v.w - __half2float(h3));
    __half2* hp = reinterpret_cast<__half2*>(hi + (size_t)i*4);
    __half2* lp = reinterpret_cast<__half2*>(lo + (size_t)i*4);
    hp[0] = __halves2half2(h0, h1); hp[1] = __halves2half2(h2, h3);
    lp[0] = __halves2half2(l0, l1); lp[1] = __halves2half2(l2, l3);
}

// ---------------- HMMA fp16 3x-split NT GEMM ----------------
// C[m,n] = sum_k A[m,k]*B[n,k].  128x128 CTA tile, BK=32, 256 threads,
// 2-stage cp.async double buffer, padded smem rows (80B) for conflict-free ldmatrix.
#define BMt 128
#define BNt 128
#define BKt 32
#define RSB 80
#define TILE_B (128*RSB)      // 10240
#define STAGE_B (4*TILE_B)    // 40960: Ah | Al | Bh | Bl
#define GSMEM  (2*STAGE_B)    // 81920

__global__ __launch_bounds__(256, 1)
void gemm_fp16x3(const __half* __restrict__ Ah, const __half* __restrict__ Al,
                 const __half* __restrict__ Bh, const __half* __restrict__ Bl,
                 float* __restrict__ C0, float* __restrict__ C1, float* __restrict__ C2)
{
    extern __shared__ char sm[];
    const uint32_t sb0 = smem_u32(sm);
    const int tid = threadIdx.x, lane = tid & 31, wid = tid >> 5;
    const int wm = wid & 1, wn = wid >> 1;          // 2 x 4 warp grid
    const int z = blockIdx.z;
    const __half* bhp = Bh + (size_t)z * Dd * Dd;
    const __half* blp = Bl + (size_t)z * Dd * Dd;
    float* C = (z == 0) ? C0 : (z == 1) ? C1 : C2;
    const int bm = blockIdx.y * BMt, bn = blockIdx.x * BNt;

    // loader mapping: thread -> (row, 2 consecutive 16B chunks)
    const int lr = tid >> 1;            // 0..127
    const int lc = (tid & 1) * 2;       // chunk 0 or 2 (of 4 per row)

    auto load_stage = [&](int s, int kt){
        const uint32_t st = sb0 + s * STAGE_B;
        const int kel = kt * BKt + lc * 8;   // element offset in K
        const __half* g0 = Ah  + (size_t)(bm + lr) * Dd + kel;
        const __half* g1 = Al  + (size_t)(bm + lr) * Dd + kel;
        const __half* g2 = bhp + (size_t)(bn + lr) * Dd + kel;
        const __half* g3 = blp + (size_t)(bn + lr) * Dd + kel;
        const uint32_t sa = st + lr * RSB + lc * 16;
        cpasync16(sa + 0*TILE_B,      g0);   cpasync16(sa + 0*TILE_B + 16, g0 + 8);
        cpasync16(sa + 1*TILE_B,      g1);   cpasync16(sa + 1*TILE_B + 16, g1 + 8);
        cpasync16(sa + 2*TILE_B,      g2);   cpasync16(sa + 2*TILE_B + 16, g2 + 8);
        cpasync16(sa + 3*TILE_B,      g3);   cpasync16(sa + 3*TILE_B + 16, g3 + 8);
    };

    float acc[4][4][4];
    #pragma unroll
    for (int i = 0; i < 4; i++)
        #pragma unroll
        for (int j = 0; j < 4; j++)
            #pragma unroll
            for (int u = 0; u < 4; u++) acc[i][j][u] = 0.f;

    // ldmatrix per-lane row offsets
    const int arow_l = (lane & 15);                     // A: row within 16-block
    const int acol   = (lane >> 4) * 16;                // A: k-half byte offset
    const int brow_l = (lane & 7) + ((lane & 16) >> 1); // B: row within 16-block
    const int bcol   = ((lane >> 3) & 1) * 16;          // B: k-half byte offset

    auto compute_stage = [&](int s){
        const uint32_t st = sb0 + s * STAGE_B;
        #pragma unroll
        for (int ks = 0; ks < 2; ks++){
            const int kb = ks * 32;   // byte offset of k16 half within 64B row
            uint32_t ah[4][4], al4[4][4], bh4[2][4], bl4[2][4];
            #pragma unroll
            for (int mt = 0; mt < 4; mt++){
                const uint32_t ra = st + (wm*64 + mt*16 + arow_l) * RSB + kb + acol;
                ldsm4(ah[mt],  ra);
                ldsm4(al4[mt], ra + TILE_B);
            }
            #pragma unroll
            for (int nb = 0; nb < 2; nb++){
                const uint32_t rb = st + 2*TILE_B + (wn*32 + nb*16 + brow_l) * RSB + kb + bcol;
                ldsm4(bh4[nb], rb);
                ldsm4(bl4[nb], rb + TILE_B);
            }
            #pragma unroll
            for (int mt = 0; mt < 4; mt++){
                #pragma unroll
                for (int nt = 0; nt < 4; nt++){
                    const int nb = nt >> 1, pr = (nt & 1) * 2;
                    uint32_t bfh[2] = { bh4[nb][pr], bh4[nb][pr+1] };
                    uint32_t bfl[2] = { bl4[nb][pr], bl4[nb][pr+1] };
                    mma16816(acc[mt][nt], ah[mt],  bfh);
                    mma16816(acc[mt][nt], al4[mt], bfh);
                    mma16816(acc[mt][nt], ah[mt],  bfl);
                }
            }
        }
    };

    const int niter = Dd / BKt;   // 64
    load_stage(0, 0); CP_COMMIT();
    for (int kt = 0; kt < niter; kt++){
        if (kt + 1 < niter){
            load_stage((kt + 1) & 1, kt + 1); CP_COMMIT();
            CP_WAIT(1);
        } else {
            CP_WAIT(0);
        }
        __syncthreads();
        compute_stage(kt & 1);
        __syncthreads();
    }

    // epilogue
    #pragma unroll
    for (int mt = 0; mt < 4; mt++){
        const int m = bm + wm*64 + mt*16 + (lane >> 2);
        #pragma unroll
        for (int nt = 0; nt < 4; nt++){
            const int n = bn + wn*32 + nt*8 + 2*(lane & 3);
            *reinterpret_cast<float2*>(C + (size_t)m * Dd + n) =
                make_float2(acc[mt][nt][0], acc[mt][nt][1]);
            *reinterpret_cast<float2*>(C + (size_t)(m + 8) * Dd + n) =
                make_float2(acc[mt][nt][2], acc[mt][nt][3]);
        }
    }
}

// ---------------- RoPE in place on q,k,v ----------------
__global__ void rope_kernel(const float* __restrict__ pf)
{
    int idx = blockIdx.x * blockDim.x + threadIdx.x;
    const int total = Bb * Ss * Hh * (HDd/2);
    if (idx >= total) return;
    int p   = idx & 31;
    int h   = (idx >> 5) & 31;
    int tok = idx >> 10;
    int s   = tok & (Ss - 1);
    float f = pf[s*32 + p];
    float sn, c;
    sincosf(f, &sn, &c);
    size_t off = (size_t)tok * Dd + h * HDd + 2 * p;
    float2* q2 = reinterpret_cast<float2*>(g_q + off);
    float2* k2 = reinterpret_cast<float2*>(g_k + off);
    float2* v2 = reinterpret_cast<float2*>(g_v + off);
    float2 a;
    a = *q2; *q2 = make_float2(a.x*c - a.y*sn, a.x*sn + a.y*c);
    a = *k2; *k2 = make_float2(a.x*c - a.y*sn, a.x*sn + a.y*c);
    a = *v2; *v2 = make_float2(a.x*c - a.y*sn, a.x*sn + a.y*c);
}

// ---------------- per-(token, head) learning-rate scalar ----------------
__global__ __launch_bounds__(256)
void lr_kernel(const float* __restrict__ x, const float* __restrict__ ilrW,
               const float* __restrict__ ilrb)
{
    __shared__ float xs[Dd];
    int row = blockIdx.x;
    for (int i = threadIdx.x; i < Dd; i += 256) xs[i] = x[(size_t)row * Dd + i];
    __syncthreads();
    int w = threadIdx.x >> 5, lane = threadIdx.x & 31;
    for (int h = w; h < Hh; h += 8){
        const float* wr = ilrW + (size_t)h * Dd;
        float s = 0.f;
        for (int m = lane; m < Dd; m += 32) s = fmaf(xs[m], wr[m], s);
        #pragma unroll
        for (int o = 16; o; o >>= 1) s += __shfl_xor_sync(0xffffffffu, s, o);
        if (lane == 0){
            float t = s + ilrb[h];
            g_lr[(size_t)row * Hh + h] = (1.0f / (1.0f + expf(-t))) * (1.0f / (float)HDd);
        }
    }
}

// ---------------- sequential TTT scan: 1 block per (b,h) ----------------
#define SR 65
__global__ __launch_bounds__(512, 1)
void scan_kernel(const float* __restrict__ lgs, const float* __restrict__ tg,
                 const float* __restrict__ tb,  const float* __restrict__ W0,
                 const float* __restrict__ b0)
{
    __shared__ float Wm[64*64];
    __shared__ float XQ[16*SR], XK[16*SR], XV[16*SR];
    __shared__ float Zs[16*SR], ZQ[16*SR], Gr[16*SR];
    __shared__ float bb[64], bnew[64], gv[64], bev[64];
    __shared__ float Attn[16][16], Cc[16][17];
    __shared__ float lrv[16], gsv[16];

    const int bh = blockIdx.x;
    const int b = bh >> 5, h = bh & 31;
    const int tid = threadIdx.x, w = tid >> 5, lane = tid & 31;

    for (int i = tid; i < 4096; i += 512) Wm[i] = W0[h*4096 + i];
    if (tid < 64){ bb[tid] = b0[h*64 + tid]; gv[tid] = tg[h*64 + tid]; bev[tid] = tb[h*64 + tid]; }
    if (tid < 16) gsv[tid] = fmaxf(1.0f / (float)(tid + 1) + lgs[tid], 0.0f);
    __syncthreads();

    const size_t base = (size_t)b * Ss * Dd + h * HDd;

    for (int n = 0; n < Nsteps; n++){
        for (int i = tid; i < 16*64; i += 512){
            int r = i >> 6, c = i & 63;
            size_t gi = base + (size_t)(n*MBb + r) * Dd + c;
            XQ[r*SR + c] = g_q[gi];
            XK[r*SR + c] = g_k[gi];
            XV[r*SR + c] = g_v[gi];
        }
        if (tid < 16) lrv[tid] = g_lr[((size_t)b * Ss + n*MBb + tid) * Hh + h];
        __syncthreads();

        {
            const int i = w;
            float z0 = bb[lane], z1 = bb[lane+32], p0 = 0.f, p1 = 0.f;
            #pragma unroll 8
            for (int kk = 0; kk < 64; kk++){
                float w0 = Wm[kk*64 + lane], w1 = Wm[kk*64 + lane + 32];
                float xk = XK[i*SR + kk], xq = XQ[i*SR + kk];
                z0 = fmaf(xk, w0, z0); z1 = fmaf(xk, w1, z1);
                p0 = fmaf(xq, w0, p0); p1 = fmaf(xq, w1, p1);
            }
            Zs[i*SR + lane] = z0; Zs[i*SR + lane + 32] = z1;
            ZQ[i*SR + lane] = p0; ZQ[i*SR + lane + 32] = p1;
            if (lane < 16){
                float s = 0.f;
                #pragma unroll 8
                for (int kk = 0; kk < 64; kk++) s = fmaf(XQ[i*SR + kk], XK[lane*SR + kk], s);
                Attn[i][lane] = s;
            }
        }
        __syncthreads();

        {
            const int i = w;
            float z0 = Zs[i*SR + lane], z1 = Zs[i*SR + lane + 32];
            float s = z0 + z1;
            #pragma unroll
            for (int o = 16; o; o >>= 1) s += __shfl_xor_sync(0xffffffffu, s, o);
            float mu = s * (1.0f/64.0f);
            float d0 = z0 - mu, d1 = z1 - mu;
            float vs = d0*d0 + d1*d1;
            #pragma unroll
            for (int o = 16; o; o >>= 1) vs += __shfl_xor_sync(0xffffffffu, vs, o);
            float rstd = rsqrtf(vs * (1.0f/64.0f) + EPSf);
            float zh0 = d0 * rstd, zh1 = d1 * rstd;
            float g0 = gv[lane], g1 = gv[lane+32];
            float dy0 = fmaf(g0, zh0, bev[lane])    - (XV[i*SR + lane]    - XK[i*SR + lane]);
            float dy1 = fmaf(g1, zh1, bev[lane+32]) - (XV[i*SR + lane+32] - XK[i*SR + lane+32]);
            float dz0 = dy0 * g0, dz1 = dy1 * g1;
            float m1 = dz0 + dz1;
            float m2 = fmaf(dz0, zh0, dz1*zh1);
            #pragma unroll
            for (int o = 16; o; o >>= 1){
                m1 += __shfl_xor_sync(0xffffffffu, m1, o);
                m2 += __shfl_xor_sync(0xffffffffu, m2, o);
            }
            m1 *= (1.0f/64.0f); m2 *= (1.0f/64.0f);
            Gr[i*SR + lane]      = (dz0 - m1 - zh0*m2) * rstd;
            Gr[i*SR + lane + 32] = (dz1 - m1 - zh1*m2) * rstd;
        }
        if (tid < 256){
            int i = tid >> 4, j = tid & 15;
            Cc[i][j] = (j <= i) ? gsv[i] * lrv[j] * (Attn[i][j] + 1.0f) : 0.0f;
        }
        __syncthreads();

        {
            const int i = w;
            float zb0 = ZQ[i*SR + lane]      + bb[lane];
            float zb1 = ZQ[i*SR + lane + 32] + bb[lane + 32];
            for (int j = 0; j <= i; j++){
                float c = Cc[i][j];
                zb0 = fmaf(-c, Gr[j*SR + lane],      zb0);
                zb1 = fmaf(-c, Gr[j*SR + lane + 32], zb1);
            }
            float s = zb0 + zb1;
            #pragma unroll
            for (int o = 16; o; o >>= 1) s += __shfl_xor_sync(0xffffffffu, s, o);
            float mu = s * (1.0f/64.0f);
            float d0 = zb0 - mu, d1 = zb1 - mu;
            float vs = d0*d0 + d1*d1;
            #pragma unroll
            for (int o = 16; o; o >>= 1) vs += __shfl_xor_sync(0xffffffffu, vs, o);
            float rstd = rsqrtf(vs * (1.0f/64.0f) + EPSf);
            size_t go = base + (size_t)(n*MBb + i) * Dd;
            g_y[go + lane]      = XQ[i*SR + lane]      + fmaf(gv[lane]      * d0, rstd, bev[lane]);
            g_y[go + lane + 32] = XQ[i*SR + lane + 32] + fmaf(gv[lane + 32] * d1, rstd, bev[lane + 32]);
        }
        {
            float le = gsv[15];
            #pragma unroll
            for (int q2 = 0; q2 < 4; q2++){
                int kr = w*4 + q2;
                float a0 = 0.f, a1 = 0.f;
                #pragma unroll
                for (int j = 0; j < 16; j++){
                    float t = le * lrv[j] * XK[j*SR + kr];
                    a0 = fmaf(t, Gr[j*SR + lane],      a0);
                    a1 = fmaf(t, Gr[j*SR + lane + 32], a1);
                }
                Wm[kr*64 + lane]      -= a0;
                Wm[kr*64 + lane + 32] -= a1;
            }
            if (tid < 64){
                float a = 0.f;
                #pragma unroll
                for (int j = 0; j < 16; j++) a = fmaf(le * lrv[j], Gr[j*SR + tid], a);
                bnew[tid] = bb[tid] - a;
            }
        }
        __syncthreads();
        if (tid < 64) bb[tid] = bnew[tid];
        __syncthreads();
    }
}

// ---------------- final layernorm over D, writes fp16 hi/lo splits ----------------
__global__ __launch_bounds__(256)
void postln_split_kernel(const float* __restrict__ yin, const float* __restrict__ gmm,
                         const float* __restrict__ bta)
{
    __shared__ float red[8];
    int row = blockIdx.x, tid = threadIdx.x;
    const float* r = yin + (size_t)row * Dd;
    float vals[8];
    float s = 0.f;
    #pragma unroll
    for (int i = 0; i < 8; i++){ vals[i] = r[tid + 256*i]; s += vals[i]; }
    #pragma unroll
    for (int o = 16; o; o >>= 1) s += __shfl_xor_sync(0xffffffffu, s, o);
    if ((tid & 31) == 0) red[tid >> 5] = s;
    __syncthreads();
    float tot = 0.f;
    #pragma unroll
    for (int i = 0; i < 8; i++) tot += red[i];
    float mu = tot * (1.0f / (float)Dd);
    __syncthreads();
    float vs = 0.f;
    #pragma unroll
    for (int i = 0; i < 8; i++){ float d = vals[i] - mu; vs = fmaf(d, d, vs); }
    #pragma unroll
    for (int o = 16; o; o >>= 1) vs += __shfl_xor_sync(0xffffffffu, vs, o);
    if ((tid & 31) == 0) red[tid >> 5] = vs;
    __syncthreads();
    float vtot = 0.f;
    #pragma unroll
    for (int i = 0; i < 8; i++) vtot += red[i];
    float rstd = rsqrtf(vtot * (1.0f / (float)Dd) + EPSf);
    #pragma unroll
    for (int i = 0; i < 8; i++){
        int c = tid + 256*i;
        float val = fmaf(gmm[c] * (vals[i] - mu), rstd, bta[c]);
        __half h = __float2half_rn(val);
        g_xh[(size_t)row * Dd + c] = h;
        g_xl[(size_t)row * Dd + c] = __float2half_rn(val - __half2float(h));
    }
}

// ---------------- launch ----------------
extern "C" void kernel_launch(void* const* d_in, const int* in_sizes, int n_in,
                              void* d_out, int out_size)
{
    const float* x    = (const float*)d_in[0];
    const float* pf   = (const float*)d_in[1];
    const float* Wq   = (const float*)d_in[2];
    const float* Wk   = (const float*)d_in[3];
    const float* Wv   = (const float*)d_in[4];
    const float* Wo   = (const float*)d_in[5];
    const float* pg   = (const float*)d_in[6];
    const float* pb   = (const float*)d_in[7];
    const float* ilrW = (const float*)d_in[8];
    const float* ilrb = (const float*)d_in[9];
    const float* lgs  = (const float*)d_in[10];
    const float* tg   = (const float*)d_in[11];
    const float* tb   = (const float*)d_in[12];
    const float* W0   = (const float*)d_in[13];
    const float* b0   = (const float*)d_in[14];
    float* outp = (float*)d_out;

    float *qp, *kp, *vp, *yp;
    __half *xh, *xl, *wh, *wl;
    cudaGetSymbolAddress((void**)&qp, g_q);
    cudaGetSymbolAddress((void**)&kp, g_k);
    cudaGetSymbolAddress((void**)&vp, g_v);
    cudaGetSymbolAddress((void**)&yp, g_y);
    cudaGetSymbolAddress((void**)&xh, g_xh);
    cudaGetSymbolAddress((void**)&xl, g_xl);
    cudaGetSymbolAddress((void**)&wh, g_wh);
    cudaGetSymbolAddress((void**)&wl, g_wl);

    cudaFuncSetAttribute(gemm_fp16x3, cudaFuncAttributeMaxDynamicSharedMemorySize, GSMEM);

    const int M = Bb * Ss;               // 4096
    const int nw4 = (Dd * Dd) / 4;
    const int nx4 = (M * Dd) / 4;

    // fp16 hi/lo splits
    split_kernel<<<(nx4 + 255)/256, 256>>>(x,  xh, xl, nx4);
    split_kernel<<<(nw4 + 255)/256, 256>>>(Wq, wh + 0*(size_t)Dd*Dd, wl + 0*(size_t)Dd*Dd, nw4);
    split_kernel<<<(nw4 + 255)/256, 256>>>(Wk, wh + 1*(size_t)Dd*Dd, wl + 1*(size_t)Dd*Dd, nw4);
    split_kernel<<<(nw4 + 255)/256, 256>>>(Wv, wh + 2*(size_t)Dd*Dd, wl + 2*(size_t)Dd*Dd, nw4);

    // fused q/k/v projections on tensor cores
    dim3 ggrid(Dd / BNt, M / BMt, 3);    // (16, 32, 3)
    gemm_fp16x3<<<ggrid, 256, GSMEM>>>(xh, xl, wh, wl, qp, kp, vp);

    const int rope_total = Bb * Ss * Hh * (HDd/2);
    rope_kernel<<<(rope_total + 255) / 256, 256>>>(pf);

    lr_kernel<<<M, 256>>>(x, ilrW, ilrb);

    scan_kernel<<<Bb * Hh, 512>>>(lgs, tg, tb, W0, b0);

    // post layernorm fused with fp16 split (writes g_xh/g_xl)
    postln_split_kernel<<<M, 256>>>(yp, pg, pb);

    // output projection
    split_kernel<<<(nw4 + 255)/256, 256>>>(Wo, wh, wl, nw4);
    dim3 ogrid(Dd / BNt, M / BMt, 1);
    gemm_fp16x3<<<ogrid, 256, GSMEM>>>(xh, xl, wh, wl, outp, outp, outp);
}

// round 4
// speedup vs baseline: 2.1613x; 1.2299x over previous
#include <cuda_runtime.h>
#include <cuda_fp16.h>
#include <cstdint>
#include <cstdio>

#define Bb   2
#define Ss   2048
#define Dd   2048
#define Hh   32
#define HDd  64
#define MBb  16
#define Nsteps 128
#define EPSf 1e-5f

typedef unsigned long long ull;

// ---------------- scratch (static device arrays; no allocation) ----------------
__device__ float  g_q[Bb*Ss*Dd];
__device__ float  g_k[Bb*Ss*Dd];
__device__ float  g_v[Bb*Ss*Dd];
__device__ float  g_y[Bb*Ss*Dd];
__device__ float  g_lr[Bb*Hh*Ss];     // h-major: [(b*Hh+h)*Ss + s]
__device__ __half g_xh[Bb*Ss*Dd];
__device__ __half g_xl[Bb*Ss*Dd];
__device__ __half g_wh[3*Dd*Dd];
__device__ __half g_wl[3*Dd*Dd];

// ---------------- PTX helpers ----------------
__device__ __forceinline__ uint32_t smem_u32(const void* p){
    uint32_t a;
    asm("{ .reg .u64 t; cvta.to.shared.u64 t, %1; cvt.u32.u64 %0, t; }" : "=r"(a) : "l"(p));
    return a;
}
__device__ __forceinline__ void cpasync16(uint32_t s, const void* g){
    asm volatile("cp.async.cg.shared.global [%0], [%1], 16;" :: "r"(s), "l"(g) : "memory");
}
#define CP_COMMIT() asm volatile("cp.async.commit_group;" ::: "memory")
#define CP_WAIT(n)  asm volatile("cp.async.wait_group %0;" :: "n"(n) : "memory")

__device__ __forceinline__ void ldsm4(uint32_t* r, uint32_t a){
    asm volatile("ldmatrix.sync.aligned.m8n8.x4.shared.b16 {%0,%1,%2,%3}, [%4];"
        : "=r"(r[0]), "=r"(r[1]), "=r"(r[2]), "=r"(r[3]) : "r"(a));
}
__device__ __forceinline__ void mma16816(float* d, const uint32_t* a, const uint32_t* b){
    asm volatile("mma.sync.aligned.m16n8k16.row.col.f32.f16.f16.f32 "
        "{%0,%1,%2,%3}, {%4,%5,%6,%7}, {%8,%9}, {%0,%1,%2,%3};"
        : "+f"(d[0]), "+f"(d[1]), "+f"(d[2]), "+f"(d[3])
        : "r"(a[0]), "r"(a[1]), "r"(a[2]), "r"(a[3]), "r"(b[0]), "r"(b[1]));
}
__device__ __forceinline__ ull pk2(float lo, float hi){
    ull r; asm("mov.b64 %0, {%1, %2};" : "=l"(r) : "f"(lo), "f"(hi)); return r;
}
__device__ __forceinline__ ull ffma2(ull a, ull b, ull c){
    ull d; asm("fma.rn.f32x2 %0, %1, %2, %3;" : "=l"(d) : "l"(a), "l"(b), "l"(c)); return d;
}
__device__ __forceinline__ void up2(ull v, float& lo, float& hi){
    asm("mov.b64 {%0, %1}, %2;" : "=f"(lo), "=f"(hi) : "l"(v));
}
__device__ __forceinline__ ull dup2(float x){ return pk2(x, x); }

// ---------------- fp16 hi/lo split kernel ----------------
__global__ __launch_bounds__(256)
void split_kernel(const float* __restrict__ src, __half* __restrict__ hi,
                  __half* __restrict__ lo, int n4)
{
    int i = blockIdx.x * blockDim.x + threadIdx.x;
    if (i >= n4) return;
    float4 v = reinterpret_cast<const float4*>(src)[i];
    __half h0 = __float2half_rn(v.x), h1 = __float2half_rn(v.y);
    __half h2 = __float2half_rn(v.z), h3 = __float2half_rn(v.w);
    __half l0 = __float2half_rn(v.x - __half2float(h0));
    __half l1 = __float2half_rn(v.y - __half2float(h1));
    __half l2 = __float2half_rn(v.z - __half2float(h2));
    __half l3 = __float2half_rn(v.w - __half2float(h3));
    __half2* hp = reinterpret_cast<__half2*>(hi + (size_t)i*4);
    __half2* lp = reinterpret_cast<__half2*>(lo + (size_t)i*4);
    hp[0] = __halves2half2(h0, h1); hp[1] = __halves2half2(h2, h3);
    lp[0] = __halves2half2(l0, l1); lp[1] = __halves2half2(l2, l3);
}

// ---------------- HMMA fp16 3x-split NT GEMM: 3-stage pipeline ----------------
#define BMt 128
#define BNt 128
#define BKt 32
#define RSB 80
#define TILE_B (128*RSB)      // 10240
#define STAGE_B (4*TILE_B)    // 40960: Ah | Al | Bh | Bl
#define GSMEM  (3*STAGE_B)    // 122880

__global__ __launch_bounds__(256, 1)
void gemm_fp16x3(const __half* __restrict__ Ah, const __half* __restrict__ Al,
                 const __half* __restrict__ Bh, const __half* __restrict__ Bl,
                 float* __restrict__ C0, float* __restrict__ C1, float* __restrict__ C2)
{
    extern __shared__ char sm[];
    const uint32_t sb0 = smem_u32(sm);
    const int tid = threadIdx.x, lane = tid & 31, wid = tid >> 5;
    const int wm = wid & 1, wn = wid >> 1;
    const int z = blockIdx.z;
    const __half* bhp = Bh + (size_t)z * Dd * Dd;
    const __half* blp = Bl + (size_t)z * Dd * Dd;
    float* C = (z == 0) ? C0 : (z == 1) ? C1 : C2;
    const int bm = blockIdx.y * BMt, bn = blockIdx.x * BNt;

    const int lr = tid >> 1;
    const int lc = (tid & 1) * 2;

    auto load_stage = [&](int s, int kt){
        const uint32_t st = sb0 + s * STAGE_B;
        const int kel = kt * BKt + lc * 8;
        const __half* g0 = Ah  + (size_t)(bm + lr) * Dd + kel;
        const __half* g1 = Al  + (size_t)(bm + lr) * Dd + kel;
        const __half* g2 = bhp + (size_t)(bn + lr) * Dd + kel;
        const __half* g3 = blp + (size_t)(bn + lr) * Dd + kel;
        const uint32_t sa = st + lr * RSB + lc * 16;
        cpasync16(sa + 0*TILE_B,      g0);   cpasync16(sa + 0*TILE_B + 16, g0 + 8);
        cpasync16(sa + 1*TILE_B,      g1);   cpasync16(sa + 1*TILE_B + 16, g1 + 8);
        cpasync16(sa + 2*TILE_B,      g2);   cpasync16(sa + 2*TILE_B + 16, g2 + 8);
        cpasync16(sa + 3*TILE_B,      g3);   cpasync16(sa + 3*TILE_B + 16, g3 + 8);
    };

    float acc[4][4][4];
    #pragma unroll
    for (int i = 0; i < 4; i++)
        #pragma unroll
        for (int j = 0; j < 4; j++)
            #pragma unroll
            for (int u = 0; u < 4; u++) acc[i][j][u] = 0.f;

    const int arow_l = (lane & 15);
    const int acol   = (lane >> 4) * 16;
    const int brow_l = (lane & 7) + ((lane & 16) >> 1);
    const int bcol   = ((lane >> 3) & 1) * 16;

    auto compute_stage = [&](int s){
        const uint32_t st = sb0 + s * STAGE_B;
        #pragma unroll
        for (int ks = 0; ks < 2; ks++){
            const int kb = ks * 32;
            uint32_t ah[4][4], al4[4][4], bh4[2][4], bl4[2][4];
            #pragma unroll
            for (int mt = 0; mt < 4; mt++){
                const uint32_t ra = st + (wm*64 + mt*16 + arow_l) * RSB + kb + acol;
                ldsm4(ah[mt],  ra);
                ldsm4(al4[mt], ra + TILE_B);
            }
            #pragma unroll
            for (int nb = 0; nb < 2; nb++){
                const uint32_t rb = st + 2*TILE_B + (wn*32 + nb*16 + brow_l) * RSB + kb + bcol;
                ldsm4(bh4[nb], rb);
                ldsm4(bl4[nb], rb + TILE_B);
            }
            #pragma unroll
            for (int mt = 0; mt < 4; mt++){
                #pragma unroll
                for (int nt = 0; nt < 4; nt++){
                    const int nb = nt >> 1, pr = (nt & 1) * 2;
                    uint32_t bfh[2] = { bh4[nb][pr], bh4[nb][pr+1] };
                    uint32_t bfl[2] = { bl4[nb][pr], bl4[nb][pr+1] };
                    mma16816(acc[mt][nt], ah[mt],  bfh);
                    mma16816(acc[mt][nt], al4[mt], bfh);
                    mma16816(acc[mt][nt], ah[mt],  bfl);
                }
            }
        }
    };

    const int niter = Dd / BKt;   // 64
    load_stage(0, 0); CP_COMMIT();
    load_stage(1, 1); CP_COMMIT();
    for (int kt = 0; kt < niter; kt++){
        CP_WAIT(1);                 // stage kt ready
        __syncthreads();
        if (kt + 2 < niter){ load_stage((kt + 2) % 3, kt + 2); CP_COMMIT(); }
        else               { CP_COMMIT(); }
        compute_stage(kt % 3);
    }

    #pragma unroll
    for (int mt = 0; mt < 4; mt++){
        const int m = bm + wm*64 + mt*16 + (lane >> 2);
        #pragma unroll
        for (int nt = 0; nt < 4; nt++){
            const int n = bn + wn*32 + nt*8 + 2*(lane & 3);
            *reinterpret_cast<float2*>(C + (size_t)m * Dd + n) =
                make_float2(acc[mt][nt][0], acc[mt][nt][1]);
            *reinterpret_cast<float2*>(C + (size_t)(m + 8) * Dd + n) =
                make_float2(acc[mt][nt][2], acc[mt][nt][3]);
        }
    }
}

// ---------------- RoPE in place on q,k,v ----------------
__global__ void rope_kernel(const float* __restrict__ pf)
{
    int idx = blockIdx.x * blockDim.x + threadIdx.x;
    const int total = Bb * Ss * Hh * (HDd/2);
    if (idx >= total) return;
    int p   = idx & 31;
    int h   = (idx >> 5) & 31;
    int tok = idx >> 10;
    int s   = tok & (Ss - 1);
    float f = pf[s*32 + p];
    float sn, c;
    sincosf(f, &sn, &c);
    size_t off = (size_t)tok * Dd + h * HDd + 2 * p;
    float2* q2 = reinterpret_cast<float2*>(g_q + off);
    float2* k2 = reinterpret_cast<float2*>(g_k + off);
    float2* v2 = reinterpret_cast<float2*>(g_v + off);
    float2 a;
    a = *q2; *q2 = make_float2(a.x*c - a.y*sn, a.x*sn + a.y*c);
    a = *k2; *k2 = make_float2(a.x*c - a.y*sn, a.x*sn + a.y*c);
    a = *v2; *v2 = make_float2(a.x*c - a.y*sn, a.x*sn + a.y*c);
}

// ---------------- learning-rate scalars (h-major output) ----------------
__global__ __launch_bounds__(256)
void lr_kernel(const float* __restrict__ x, const float* __restrict__ ilrW,
               const float* __restrict__ ilrb)
{
    __shared__ float xs[Dd];
    int row = blockIdx.x;                 // token index in [0, B*S)
    for (int i = threadIdx.x; i < Dd; i += 256) xs[i] = x[(size_t)row * Dd + i];
    __syncthreads();
    int w = threadIdx.x >> 5, lane = threadIdx.x & 31;
    int b = row >> 11, s = row & (Ss - 1);
    for (int h = w; h < Hh; h += 8){
        const float* wr = ilrW + (size_t)h * Dd;
        float sum = 0.f;
        for (int m = lane; m < Dd; m += 32) sum = fmaf(xs[m], wr[m], sum);
        #pragma unroll
        for (int o = 16; o; o >>= 1) sum += __shfl_xor_sync(0xffffffffu, sum, o);
        if (lane == 0){
            float t = sum + ilrb[h];
            g_lr[((size_t)b * Hh + h) * Ss + s] =
                (1.0f / (1.0f + expf(-t))) * (1.0f / (float)HDd);
        }
    }
}

// ---------------- sequential TTT scan v2: warp-specialized ----------------
// smem layout (floats):
//  XQ[2][16*68], XK[2][16*68], XV[2][16*68]  (cp.async double buffer)
//  Wm[64*64], Gr[16*66], bbv[64], bnw[64], gvv[64], bev[64],
//  Cc[16*17], lrs[2*16], gsv[16]
#define SR2 68
#define TILEF (16*SR2)         // 1088
#define GRS 66
#define SCAN_SMEM_FLOATS (3*2*TILEF + 4096 + 16*GRS + 4*64 + 16*17 + 32 + 16)
#define SCAN_SMEM_BYTES  (SCAN_SMEM_FLOATS*4)

__global__ __launch_bounds__(512, 1)
void scan_kernel(const float* __restrict__ lgs, const float* __restrict__ tg,
                 const float* __restrict__ tb,  const float* __restrict__ W0,
                 const float* __restrict__ b0)
{
    extern __shared__ float sms[];
    float* XQs = sms;                 // [2][TILEF]
    float* XKs = XQs + 2*TILEF;
    float* XVs = XKs + 2*TILEF;
    float* Wm  = XVs + 2*TILEF;       // 4096
    float* Grs = Wm + 4096;           // 16*66
    float* bbv = Grs + 16*GRS;        // 64
    float* bnw = bbv + 64;
    float* gvv = bnw + 64;
    float* bev = gvv + 64;
    float* Ccs = bev + 64;            // 16*17
    float* lrs = Ccs + 16*17;         // 2*16
    float* gsv = lrs + 32;            // 16

    const int bh = blockIdx.x;
    const int b = bh >> 5, h = bh & 31;
    const int tid = threadIdx.x, w = tid >> 5, lane = tid & 31;

    for (int i = tid; i < 4096; i += 512) Wm[i] = W0[h*4096 + i];
    if (tid < 64){ bbv[tid] = b0[h*64 + tid]; gvv[tid] = tg[h*64 + tid]; bev[tid] = tb[h*64 + tid]; }
    if (tid < 16) gsv[tid] = fmaxf(1.0f / (float)(tid + 1) + lgs[tid], 0.0f);

    const size_t base = (size_t)b * Ss * Dd + h * HDd;
    const float* lrg = g_lr + ((size_t)b * Hh + h) * Ss;

    const uint32_t sXQ = smem_u32(XQs), sXK = smem_u32(XKs), sXV = smem_u32(XVs);
    const uint32_t sLR = smem_u32(lrs);

    auto prefetch = [&](int n){
        const int bs = n & 1;
        #pragma unroll
        for (int pass = 0; pass < 2; pass++){
            int idx = tid + pass * 512;
            if (idx >= 768) break;
            int tile = idx >> 8;            // 0=Q,1=K,2=V
            int r = (idx >> 4) & 15;
            int c = idx & 15;
            const float* gp = (tile == 0 ? g_q : tile == 1 ? g_k : g_v)
                              + base + (size_t)(n*MBb + r) * Dd + c*4;
            uint32_t sa = (tile == 0 ? sXQ : tile == 1 ? sXK : sXV)
                          + (bs*TILEF + r*SR2 + c*4) * 4;
            cpasync16(sa, gp);
        }
        if (tid < 4) cpasync16(sLR + (bs*16 + tid*4)*4, lrg + n*MBb + tid*4);
    };

    prefetch(0); CP_COMMIT();

    // persistent per-warp registers (warps 0..7)
    ull z0 = 0, z1 = 0, p0 = 0, p1 = 0;
    float2 bb2 = make_float2(0.f, 0.f), gv2 = make_float2(0.f, 0.f), be2 = make_float2(0.f, 0.f);

    for (int n = 0; n < Nsteps; n++){
        CP_WAIT(0);
        __syncthreads();                    // tiles[n&1], lrs[n&1] ready; prior-iter writes settled
        const int bs = n & 1;
        if (n + 1 < Nsteps) prefetch(n + 1);
        CP_COMMIT();

        const float* XQb = XQs + bs*TILEF;
        const float* XKb = XKs + bs*TILEF;
        const float* XVb = XVs + bs*TILEF;
        const float* lrb = lrs + bs*16;

        // ================= phase A =================
        if (w < 8){
            const int r0 = 2*w, r1 = r0 + 1;
            bb2 = *reinterpret_cast<const float2*>(bbv + 2*lane);
            gv2 = *reinterpret_cast<const float2*>(gvv + 2*lane);
            be2 = *reinterpret_cast<const float2*>(bev + 2*lane);
            z0 = pk2(bb2.x, bb2.y); z1 = z0; p0 = 0; p1 = 0;
            #pragma unroll 4
            for (int kk = 0; kk < 64; kk += 2){
                float2 wa = *reinterpret_cast<const float2*>(Wm + kk*64 + 2*lane);
                float2 wb = *reinterpret_cast<const float2*>(Wm + (kk+1)*64 + 2*lane);
                float2 k0v = *reinterpret_cast<const float2*>(XKb + r0*SR2 + kk);
                float2 k1v = *reinterpret_cast<const float2*>(XKb + r1*SR2 + kk);
                float2 q0v = *reinterpret_cast<const float2*>(XQb + r0*SR2 + kk);
                float2 q1v = *reinterpret_cast<const float2*>(XQb + r1*SR2 + kk);
                ull wau = pk2(wa.x, wa.y), wbu = pk2(wb.x, wb.y);
                z0 = ffma2(dup2(k0v.x), wau, z0); z0 = ffma2(dup2(k0v.y), wbu, z0);
                z1 = ffma2(dup2(k1v.x), wau, z1); z1 = ffma2(dup2(k1v.y), wbu, z1);
                p0 = ffma2(dup2(q0v.x), wau, p0); p0 = ffma2(dup2(q0v.y), wbu, p0);
                p1 = ffma2(dup2(q1v.x), wau, p1); p1 = ffma2(dup2(q1v.y), wbu, p1);
            }
        } else {
            // Attn rows 2u, 2u+1  ->  Cc
            const int u = w - 8;
            const int r0 = 2*u, r1 = r0 + 1;
            const int j = lane & 15, half = lane >> 4;
            const float* xkr = XKb + j*SR2 + half*32;
            const float* xq0 = XQb + r0*SR2 + half*32;
            const float* xq1 = XQb + r1*SR2 + half*32;
            float s0 = 0.f, s1v = 0.f;
            #pragma unroll 8
            for (int t = 0; t < 32; t++){
                float xk = xkr[t];
                s0  = fmaf(xq0[t], xk, s0);
                s1v = fmaf(xq1[t], xk, s1v);
            }
            s0  += __shfl_down_sync(0xffffffffu, s0, 16);
            s1v += __shfl_down_sync(0xffffffffu, s1v, 16);
            if (lane < 16){
                float lrj = lrb[j];
                if (j <= r0) Ccs[r0*17 + j] = gsv[r0] * lrj * (s0 + 1.f);
                if (j <= r1) Ccs[r1*17 + j] = gsv[r1] * lrj * (s1v + 1.f);
            }
        }
        __syncthreads();

        // ================= phase B: grad (warps 0..7) =================
        if (w < 8){
            const int r0 = 2*w, r1 = r0 + 1;
            #pragma unroll
            for (int rr = 0; rr < 2; rr++){
                const int r = rr ? r1 : r0;
                float zx, zy; up2(rr ? z1 : z0, zx, zy);
                float s1r = zx + zy, s2r = zx*zx + zy*zy;
                #pragma unroll
                for (int o = 16; o; o >>= 1){
                    s1r += __shfl_xor_sync(0xffffffffu, s1r, o);
                    s2r += __shfl_xor_sync(0xffffffffu, s2r, o);
                }
                float mu = s1r * (1.0f/64.0f);
                float var = s2r * (1.0f/64.0f) - mu*mu;
                float rstd = rsqrtf(var + EPSf);
                float zhx = (zx - mu) * rstd, zhy = (zy - mu) * rstd;
                float2 xv = *reinterpret_cast<const float2*>(XVb + r*SR2 + 2*lane);
                float2 xk = *reinterpret_cast<const float2*>(XKb + r*SR2 + 2*lane);
                float dyx = fmaf(gv2.x, zhx, be2.x) - (xv.x - xk.x);
                float dyy = fmaf(gv2.y, zhy, be2.y) - (xv.y - xk.y);
                float dzx = dyx * gv2.x, dzy = dyy * gv2.y;
                float m1 = dzx + dzy, m2 = fmaf(dzx, zhx, dzy*zhy);
                #pragma unroll
                for (int o = 16; o; o >>= 1){
                    m1 += __shfl_xor_sync(0xffffffffu, m1, o);
                    m2 += __shfl_xor_sync(0xffffffffu, m2, o);
                }
                m1 *= (1.0f/64.0f); m2 *= (1.0f/64.0f);
                float grx = (dzx - m1 - zhx*m2) * rstd;
                float gry = (dzy - m1 - zhy*m2) * rstd;
                *reinterpret_cast<float2*>(Grs + r*GRS + 2*lane) = make_float2(grx, gry);
            }
        }
        __syncthreads();

        // ================= phase C =================
        if (w < 8){
            // Z_bar + ln_fwd + output
            #pragma unroll
            for (int rr = 0; rr < 2; rr++){
                const int r = 2*w + rr;
                float px, py; up2(rr ? p1 : p0, px, py);
                float ax = px + bb2.x, ay = py + bb2.y;
                for (int j = 0; j <= r; j++){
                    float c = Ccs[r*17 + j];
                    float2 gr = *reinterpret_cast<const float2*>(Grs + j*GRS + 2*lane);
                    ax = fmaf(-c, gr.x, ax);
                    ay = fmaf(-c, gr.y, ay);
                }
                float s1r = ax + ay, s2r = ax*ax + ay*ay;
                #pragma unroll
                for (int o = 16; o; o >>= 1){
                    s1r += __shfl_xor_sync(0xffffffffu, s1r, o);
                    s2r += __shfl_xor_sync(0xffffffffu, s2r, o);
                }
                float mu = s1r * (1.0f/64.0f);
                float var = s2r * (1.0f/64.0f) - mu*mu;
                float rstd = rsqrtf(var + EPSf);
                float2 xq = *reinterpret_cast<const float2*>(XQb + r*SR2 + 2*lane);
                float ox = xq.x + fmaf(gv2.x * (ax - mu), rstd, be2.x);
                float oy = xq.y + fmaf(gv2.y * (ay - mu), rstd, be2.y);
                size_t go = base + (size_t)(n*MBb + r) * Dd;
                *reinterpret_cast<float2*>(g_y + go + 2*lane) = make_float2(ox, oy);
            }
        } else {
            // W update (8 kr rows per warp) + b update (warp 8)
            const int u = w - 8;
            const int kr0 = u * 8;
            const float le = gsv[15];
            ull wacc[8];
            #pragma unroll
            for (int q = 0; q < 8; q++) wacc[q] = 0;
            float bx = 0.f, by = 0.f;
            if (u == 0){
                float2 bb2c = *reinterpret_cast<const float2*>(bbv + 2*lane);
                bx = bb2c.x; by = bb2c.y;
            }
            #pragma unroll
            for (int j = 0; j < 16; j++){
                float2 gr = *reinterpret_cast<const float2*>(Grs + j*GRS + 2*lane);
                ull gru = pk2(gr.x, gr.y);
                float cj = le * lrb[j];
                #pragma unroll
                for (int q = 0; q < 8; q++){
                    float t = cj * XKb[j*SR2 + kr0 + q];
                    wacc[q] = ffma2(dup2(t), gru, wacc[q]);
                }
                if (u == 0){
                    bx = fmaf(-cj, gr.x, bx);
                    by = fmaf(-cj, gr.y, by);
                }
            }
            #pragma unroll
            for (int q = 0; q < 8; q++){
                float wx, wy; up2(wacc[q], wx, wy);
                float2* wp = reinterpret_cast<float2*>(Wm + (kr0+q)*64 + 2*lane);
                float2 wv = *wp;
                wv.x -= wx; wv.y -= wy;
                *wp = wv;
            }
            if (u == 0) *reinterpret_cast<float2*>(bnw + 2*lane) = make_float2(bx, by);
        }
        __syncthreads();
        if (tid < 64) bbv[tid] = bnw[tid];
        // next-iter top __syncthreads covers bbv visibility
    }
}

// ---------------- final layernorm over D, writes fp16 hi/lo splits ----------------
__global__ __launch_bounds__(256)
void postln_split_kernel(const float* __restrict__ yin, const float* __restrict__ gmm,
                         const float* __restrict__ bta)
{
    __shared__ float red[8];
    int row = blockIdx.x, tid = threadIdx.x;
    const float* r = yin + (size_t)row * Dd;
    float vals[8];
    float s = 0.f;
    #pragma unroll
    for (int i = 0; i < 8; i++){ vals[i] = r[tid + 256*i]; s += vals[i]; }
    #pragma unroll
    for (int o = 16; o; o >>= 1) s += __shfl_xor_sync(0xffffffffu, s, o);
    if ((tid & 31) == 0) red[tid >> 5] = s;
    __syncthreads();
    float tot = 0.f;
    #pragma unroll
    for (int i = 0; i < 8; i++) tot += red[i];
    float mu = tot * (1.0f / (float)Dd);
    __syncthreads();
    float vs = 0.f;
    #pragma unroll
    for (int i = 0; i < 8; i++){ float d = vals[i] - mu; vs = fmaf(d, d, vs); }
    #pragma unroll
    for (int o = 16; o; o >>= 1) vs += __shfl_xor_sync(0xffffffffu, vs, o);
    if ((tid & 31) == 0) red[tid >> 5] = vs;
    __syncthreads();
    float vtot = 0.f;
    #pragma unroll
    for (int i = 0; i < 8; i++) vtot += red[i];
    float rstd = rsqrtf(vtot * (1.0f / (float)Dd) + EPSf);
    #pragma unroll
    for (int i = 0; i < 8; i++){
        int c = tid + 256*i;
        float val = fmaf(gmm[c] * (vals[i] - mu), rstd, bta[c]);
        __half hv = __float2half_rn(val);
        g_xh[(size_t)row * Dd + c] = hv;
        g_xl[(size_t)row * Dd + c] = __float2half_rn(val - __half2float(hv));
    }
}

// ---------------- launch ----------------
extern "C" void kernel_launch(void* const* d_in, const int* in_sizes, int n_in,
                              void* d_out, int out_size)
{
    const float* x    = (const float*)d_in[0];
    const float* pf   = (const float*)d_in[1];
    const float* Wq   = (const float*)d_in[2];
    const float* Wk   = (const float*)d_in[3];
    const float* Wv   = (const float*)d_in[4];
    const float* Wo   = (const float*)d_in[5];
    const float* pg   = (const float*)d_in[6];
    const float* pb   = (const float*)d_in[7];
    const float* ilrW = (const float*)d_in[8];
    const float* ilrb = (const float*)d_in[9];
    const float* lgs  = (const float*)d_in[10];
    const float* tg   = (const float*)d_in[11];
    const float* tb   = (const float*)d_in[12];
    const float* W0   = (const float*)d_in[13];
    const float* b0   = (const float*)d_in[14];
    float* outp = (float*)d_out;

    float *qp, *kp, *vp, *yp;
    __half *xh, *xl, *wh, *wl;
    cudaGetSymbolAddress((void**)&qp, g_q);
    cudaGetSymbolAddress((void**)&kp, g_k);
    cudaGetSymbolAddress((void**)&vp, g_v);
    cudaGetSymbolAddress((void**)&yp, g_y);
    cudaGetSymbolAddress((void**)&xh, g_xh);
    cudaGetSymbolAddress((void**)&xl, g_xl);
    cudaGetSymbolAddress((void**)&wh, g_wh);
    cudaGetSymbolAddress((void**)&wl, g_wl);

    cudaFuncSetAttribute(gemm_fp16x3, cudaFuncAttributeMaxDynamicSharedMemorySize, GSMEM);
    cudaFuncSetAttribute(scan_kernel, cudaFuncAttributeMaxDynamicSharedMemorySize, SCAN_SMEM_BYTES);

    const int M = Bb * Ss;               // 4096
    const int nw4 = (Dd * Dd) / 4;
    const int nx4 = (M * Dd) / 4;

    split_kernel<<<(nx4 + 255)/256, 256>>>(x,  xh, xl, nx4);
    split_kernel<<<(nw4 + 255)/256, 256>>>(Wq, wh + 0*(size_t)Dd*Dd, wl + 0*(size_t)Dd*Dd, nw4);
    split_kernel<<<(nw4 + 255)/256, 256>>>(Wk, wh + 1*(size_t)Dd*Dd, wl + 1*(size_t)Dd*Dd, nw4);
    split_kernel<<<(nw4 + 255)/256, 256>>>(Wv, wh + 2*(size_t)Dd*Dd, wl + 2*(size_t)Dd*Dd, nw4);

    dim3 ggrid(Dd / BNt, M / BMt, 3);
    gemm_fp16x3<<<ggrid, 256, GSMEM>>>(xh, xl, wh, wl, qp, kp, vp);

    const int rope_total = Bb * Ss * Hh * (HDd/2);
    rope_kernel<<<(rope_total + 255) / 256, 256>>>(pf);

    lr_kernel<<<M, 256>>>(x, ilrW, ilrb);

    scan_kernel<<<Bb * Hh, 512, SCAN_SMEM_BYTES>>>(lgs, tg, tb, W0, b0);

    postln_split_kernel<<<M, 256>>>(yp, pg, pb);

    split_kernel<<<(nw4 + 255)/256, 256>>>(Wo, wh, wl, nw4);
    dim3 ogrid(Dd / BNt, M / BMt, 1);
    gemm_fp16x3<<<ogrid, 256, GSMEM>>>(xh, xl, wh, wl, outp, outp, outp);
}

// round 5
// speedup vs baseline: 2.1672x; 1.0027x over previous
#include <cuda_runtime.h>
#include <cuda_fp16.h>
#include <cstdint>
#include <cstdio>

#define Bb   2
#define Ss   2048
#define Dd   2048
#define Hh   32
#define HDd  64
#define MBb  16
#define Nsteps 128
#define EPSf 1e-5f

typedef unsigned long long ull;

// ---------------- scratch (static device arrays; no allocation) ----------------
__device__ float  g_q[Bb*Ss*Dd];
__device__ float  g_k[Bb*Ss*Dd];
__device__ float  g_v[Bb*Ss*Dd];
__device__ float  g_y[Bb*Ss*Dd];
__device__ float  g_lr[Bb*Hh*Ss];     // h-major: [(b*Hh+h)*Ss + s]
__device__ __half g_xh[Bb*Ss*Dd];
__device__ __half g_xl[Bb*Ss*Dd];
__device__ __half g_wh[3*Dd*Dd];
__device__ __half g_wl[3*Dd*Dd];

// ---------------- PTX helpers ----------------
__device__ __forceinline__ uint32_t smem_u32(const void* p){
    uint32_t a;
    asm("{ .reg .u64 t; cvta.to.shared.u64 t, %1; cvt.u32.u64 %0, t; }" : "=r"(a) : "l"(p));
    return a;
}
__device__ __forceinline__ void cpasync16(uint32_t s, const void* g){
    asm volatile("cp.async.cg.shared.global [%0], [%1], 16;" :: "r"(s), "l"(g) : "memory");
}
#define CP_COMMIT() asm volatile("cp.async.commit_group;" ::: "memory")
#define CP_WAIT(n)  asm volatile("cp.async.wait_group %0;" :: "n"(n) : "memory")

__device__ __forceinline__ void ldsm4(uint32_t* r, uint32_t a){
    asm volatile("ldmatrix.sync.aligned.m8n8.x4.shared.b16 {%0,%1,%2,%3}, [%4];"
        : "=r"(r[0]), "=r"(r[1]), "=r"(r[2]), "=r"(r[3]) : "r"(a));
}
__device__ __forceinline__ void mma16816(float* d, const uint32_t* a, const uint32_t* b){
    asm volatile("mma.sync.aligned.m16n8k16.row.col.f32.f16.f16.f32 "
        "{%0,%1,%2,%3}, {%4,%5,%6,%7}, {%8,%9}, {%0,%1,%2,%3};"
        : "+f"(d[0]), "+f"(d[1]), "+f"(d[2]), "+f"(d[3])
        : "r"(a[0]), "r"(a[1]), "r"(a[2]), "r"(a[3]), "r"(b[0]), "r"(b[1]));
}
__device__ __forceinline__ ull pk2(float lo, float hi){
    ull r; asm("mov.b64 %0, {%1, %2};" : "=l"(r) : "f"(lo), "f"(hi)); return r;
}
__device__ __forceinline__ ull ffma2(ull a, ull b, ull c){
    ull d; asm("fma.rn.f32x2 %0, %1, %2, %3;" : "=l"(d) : "l"(a), "l"(b), "l"(c)); return d;
}
__device__ __forceinline__ void up2(ull v, float& lo, float& hi){
    asm("mov.b64 {%0, %1}, %2;" : "=f"(lo), "=f"(hi) : "l"(v));
}
__device__ __forceinline__ ull dup2(float x){ return pk2(x, x); }

// ---------------- fp16 hi/lo split kernel ----------------
__global__ __launch_bounds__(256)
void split_kernel(const float* __restrict__ src, __half* __restrict__ hi,
                  __half* __restrict__ lo, int n4)
{
    int i = blockIdx.x * blockDim.x + threadIdx.x;
    if (i >= n4) return;
    float4 v = reinterpret_cast<const float4*>(src)[i];
    __half h0 = __float2half_rn(v.x), h1 = __float2half_rn(v.y);
    __half h2 = __float2half_rn(v.z), h3 = __float2half_rn(v.w);
    __half l0 = __float2half_rn(v.x - __half2float(h0));
    __half l1 = __float2half_rn(v.y - __half2float(h1));
    __half l2 = __float2half_rn(v.z - __half2float(h2));
    __half l3 = __float2half_rn(v.w - __half2float(h3));
    __half2* hp = reinterpret_cast<__half2*>(hi + (size_t)i*4);
    __half2* lp = reinterpret_cast<__half2*>(lo + (size_t)i*4);
    hp[0] = __halves2half2(h0, h1); hp[1] = __halves2half2(h2, h3);
    lp[0] = __halves2half2(l0, l1); lp[1] = __halves2half2(l2, l3);
}

// ---------------- HMMA fp16 3x-split NT GEMM: 3-stage pipeline ----------------
#define BMt 128
#define BNt 128
#define BKt 32
#define RSB 80
#define TILE_B (128*RSB)      // 10240
#define STAGE_B (4*TILE_B)    // 40960: Ah | Al | Bh | Bl
#define GSMEM  (3*STAGE_B)    // 122880

__global__ __launch_bounds__(256, 1)
void gemm_fp16x3(const __half* __restrict__ Ah, const __half* __restrict__ Al,
                 const __half* __restrict__ Bh, const __half* __restrict__ Bl,
                 float* __restrict__ C0, float* __restrict__ C1, float* __restrict__ C2)
{
    extern __shared__ char sm[];
    const uint32_t sb0 = smem_u32(sm);
    const int tid = threadIdx.x, lane = tid & 31, wid = tid >> 5;
    const int wm = wid & 1, wn = wid >> 1;
    const int z = blockIdx.z;
    const __half* bhp = Bh + (size_t)z * Dd * Dd;
    const __half* blp = Bl + (size_t)z * Dd * Dd;
    float* C = (z == 0) ? C0 : (z == 1) ? C1 : C2;
    const int bm = blockIdx.y * BMt, bn = blockIdx.x * BNt;

    const int lr = tid >> 1;
    const int lc = (tid & 1) * 2;

    auto load_stage = [&](int s, int kt){
        const uint32_t st = sb0 + s * STAGE_B;
        const int kel = kt * BKt + lc * 8;
        const __half* g0 = Ah  + (size_t)(bm + lr) * Dd + kel;
        const __half* g1 = Al  + (size_t)(bm + lr) * Dd + kel;
        const __half* g2 = bhp + (size_t)(bn + lr) * Dd + kel;
        const __half* g3 = blp + (size_t)(bn + lr) * Dd + kel;
        const uint32_t sa = st + lr * RSB + lc * 16;
        cpasync16(sa + 0*TILE_B,      g0);   cpasync16(sa + 0*TILE_B + 16, g0 + 8);
        cpasync16(sa + 1*TILE_B,      g1);   cpasync16(sa + 1*TILE_B + 16, g1 + 8);
        cpasync16(sa + 2*TILE_B,      g2);   cpasync16(sa + 2*TILE_B + 16, g2 + 8);
        cpasync16(sa + 3*TILE_B,      g3);   cpasync16(sa + 3*TILE_B + 16, g3 + 8);
    };

    float acc[4][4][4];
    #pragma unroll
    for (int i = 0; i < 4; i++)
        #pragma unroll
        for (int j = 0; j < 4; j++)
            #pragma unroll
            for (int u = 0; u < 4; u++) acc[i][j][u] = 0.f;

    const int arow_l = (lane & 15);
    const int acol   = (lane >> 4) * 16;
    const int brow_l = (lane & 7) + ((lane & 16) >> 1);
    const int bcol   = ((lane >> 3) & 1) * 16;

    auto compute_stage = [&](int s){
        const uint32_t st = sb0 + s * STAGE_B;
        #pragma unroll
        for (int ks = 0; ks < 2; ks++){
            const int kb = ks * 32;
            uint32_t ah[4][4], al4[4][4], bh4[2][4], bl4[2][4];
            #pragma unroll
            for (int mt = 0; mt < 4; mt++){
                const uint32_t ra = st + (wm*64 + mt*16 + arow_l) * RSB + kb + acol;
                ldsm4(ah[mt],  ra);
                ldsm4(al4[mt], ra + TILE_B);
            }
            #pragma unroll
            for (int nb = 0; nb < 2; nb++){
                const uint32_t rb = st + 2*TILE_B + (wn*32 + nb*16 + brow_l) * RSB + kb + bcol;
                ldsm4(bh4[nb], rb);
                ldsm4(bl4[nb], rb + TILE_B);
            }
            #pragma unroll
            for (int mt = 0; mt < 4; mt++){
                #pragma unroll
                for (int nt = 0; nt < 4; nt++){
                    const int nb = nt >> 1, pr = (nt & 1) * 2;
                    uint32_t bfh[2] = { bh4[nb][pr], bh4[nb][pr+1] };
                    uint32_t bfl[2] = { bl4[nb][pr], bl4[nb][pr+1] };
                    mma16816(acc[mt][nt], ah[mt],  bfh);
                    mma16816(acc[mt][nt], al4[mt], bfh);
                    mma16816(acc[mt][nt], ah[mt],  bfl);
                }
            }
        }
    };

    const int niter = Dd / BKt;   // 64
    load_stage(0, 0); CP_COMMIT();
    load_stage(1, 1); CP_COMMIT();
    for (int kt = 0; kt < niter; kt++){
        CP_WAIT(1);                 // stage kt ready
        __syncthreads();
        if (kt + 2 < niter){ load_stage((kt + 2) % 3, kt + 2); CP_COMMIT(); }
        else               { CP_COMMIT(); }
        compute_stage(kt % 3);
    }

    #pragma unroll
    for (int mt = 0; mt < 4; mt++){
        const int m = bm + wm*64 + mt*16 + (lane >> 2);
        #pragma unroll
        for (int nt = 0; nt < 4; nt++){
            const int n = bn + wn*32 + nt*8 + 2*(lane & 3);
            *reinterpret_cast<float2*>(C + (size_t)m * Dd + n) =
                make_float2(acc[mt][nt][0], acc[mt][nt][1]);
            *reinterpret_cast<float2*>(C + (size_t)(m + 8) * Dd + n) =
                make_float2(acc[mt][nt][2], acc[mt][nt][3]);
        }
    }
}

// ---------------- RoPE in place on q,k,v ----------------
__global__ void rope_kernel(const float* __restrict__ pf)
{
    int idx = blockIdx.x * blockDim.x + threadIdx.x;
    const int total = Bb * Ss * Hh * (HDd/2);
    if (idx >= total) return;
    int p   = idx & 31;
    int h   = (idx >> 5) & 31;
    int tok = idx >> 10;
    int s   = tok & (Ss - 1);
    float f = pf[s*32 + p];
    float sn, c;
    sincosf(f, &sn, &c);
    size_t off = (size_t)tok * Dd + h * HDd + 2 * p;
    float2* q2 = reinterpret_cast<float2*>(g_q + off);
    float2* k2 = reinterpret_cast<float2*>(g_k + off);
    float2* v2 = reinterpret_cast<float2*>(g_v + off);
    float2 a;
    a = *q2; *q2 = make_float2(a.x*c - a.y*sn, a.x*sn + a.y*c);
    a = *k2; *k2 = make_float2(a.x*c - a.y*sn, a.x*sn + a.y*c);
    a = *v2; *v2 = make_float2(a.x*c - a.y*sn, a.x*sn + a.y*c);
}

// ---------------- learning-rate scalars (h-major output) ----------------
__global__ __launch_bounds__(256)
void lr_kernel(const float* __restrict__ x, const float* __restrict__ ilrW,
               const float* __restrict__ ilrb)
{
    __shared__ float xs[Dd];
    int row = blockIdx.x;                 // token index in [0, B*S)
    for (int i = threadIdx.x; i < Dd; i += 256) xs[i] = x[(size_t)row * Dd + i];
    __syncthreads();
    int w = threadIdx.x >> 5, lane = threadIdx.x & 31;
    int b = row >> 11, s = row & (Ss - 1);
    for (int h = w; h < Hh; h += 8){
        const float* wr = ilrW + (size_t)h * Dd;
        float sum = 0.f;
        for (int m = lane; m < Dd; m += 32) sum = fmaf(xs[m], wr[m], sum);
        #pragma unroll
        for (int o = 16; o; o >>= 1) sum += __shfl_xor_sync(0xffffffffu, sum, o);
        if (lane == 0){
            float t = sum + ilrb[h];
            g_lr[((size_t)b * Hh + h) * Ss + s] =
                (1.0f / (1.0f + expf(-t))) * (1.0f / (float)HDd);
        }
    }
}

// ---------------- sequential TTT scan v2: warp-specialized ----------------
// smem layout (floats):
//  XQ[2][16*68], XK[2][16*68], XV[2][16*68]  (cp.async double buffer)
//  Wm[64*64], Gr[16*66], bbv[64], bnw[64], gvv[64], bev[64],
//  Cc[16*17], lrs[2*16], gsv[16]
#define SR2 68
#define TILEF (16*SR2)         // 1088
#define GRS 66
#define SCAN_SMEM_FLOATS (3*2*TILEF + 4096 + 16*GRS + 4*64 + 16*17 + 32 + 16)
#define SCAN_SMEM_BYTES  (SCAN_SMEM_FLOATS*4)

__global__ __launch_bounds__(512, 1)
void scan_kernel(const float* __restrict__ lgs, const float* __restrict__ tg,
                 const float* __restrict__ tb,  const float* __restrict__ W0,
                 const float* __restrict__ b0)
{
    extern __shared__ float sms[];
    float* XQs = sms;                 // [2][TILEF]
    float* XKs = XQs + 2*TILEF;
    float* XVs = XKs + 2*TILEF;
    float* Wm  = XVs + 2*TILEF;       // 4096
    float* Grs = Wm + 4096;           // 16*66
    float* bbv = Grs + 16*GRS;        // 64
    float* bnw = bbv + 64;
    float* gvv = bnw + 64;
    float* bev = gvv + 64;
    float* Ccs = bev + 64;            // 16*17
    float* lrs = Ccs + 16*17;         // 2*16
    float* gsv = lrs + 32;            // 16

    const int bh = blockIdx.x;
    const int b = bh >> 5, h = bh & 31;
    const int tid = threadIdx.x, w = tid >> 5, lane = tid & 31;

    for (int i = tid; i < 4096; i += 512) Wm[i] = W0[h*4096 + i];
    if (tid < 64){ bbv[tid] = b0[h*64 + tid]; gvv[tid] = tg[h*64 + tid]; bev[tid] = tb[h*64 + tid]; }
    if (tid < 16) gsv[tid] = fmaxf(1.0f / (float)(tid + 1) + lgs[tid], 0.0f);

    const size_t base = (size_t)b * Ss * Dd + h * HDd;
    const float* lrg = g_lr + ((size_t)b * Hh + h) * Ss;

    const uint32_t sXQ = smem_u32(XQs), sXK = smem_u32(XKs), sXV = smem_u32(XVs);
    const uint32_t sLR = smem_u32(lrs);

    auto prefetch = [&](int n){
        const int bs = n & 1;
        #pragma unroll
        for (int pass = 0; pass < 2; pass++){
            int idx = tid + pass * 512;
            if (idx >= 768) break;
            int tile = idx >> 8;            // 0=Q,1=K,2=V
            int r = (idx >> 4) & 15;
            int c = idx & 15;
            const float* gp = (tile == 0 ? g_q : tile == 1 ? g_k : g_v)
                              + base + (size_t)(n*MBb + r) * Dd + c*4;
            uint32_t sa = (tile == 0 ? sXQ : tile == 1 ? sXK : sXV)
                          + (bs*TILEF + r*SR2 + c*4) * 4;
            cpasync16(sa, gp);
        }
        if (tid < 4) cpasync16(sLR + (bs*16 + tid*4)*4, lrg + n*MBb + tid*4);
    };

    prefetch(0); CP_COMMIT();

    // persistent per-warp registers (warps 0..7)
    ull z0 = 0, z1 = 0, p0 = 0, p1 = 0;
    float2 bb2 = make_float2(0.f, 0.f), gv2 = make_float2(0.f, 0.f), be2 = make_float2(0.f, 0.f);

    for (int n = 0; n < Nsteps; n++){
        CP_WAIT(0);
        __syncthreads();                    // tiles[n&1], lrs[n&1] ready; prior-iter writes settled
        const int bs = n & 1;
        if (n + 1 < Nsteps) prefetch(n + 1);
        CP_COMMIT();

        const float* XQb = XQs + bs*TILEF;
        const float* XKb = XKs + bs*TILEF;
        const float* XVb = XVs + bs*TILEF;
        const float* lrb = lrs + bs*16;

        // ================= phase A =================
        if (w < 8){
            const int r0 = 2*w, r1 = r0 + 1;
            bb2 = *reinterpret_cast<const float2*>(bbv + 2*lane);
            gv2 = *reinterpret_cast<const float2*>(gvv + 2*lane);
            be2 = *reinterpret_cast<const float2*>(bev + 2*lane);
            z0 = pk2(bb2.x, bb2.y); z1 = z0; p0 = 0; p1 = 0;
            #pragma unroll 4
            for (int kk = 0; kk < 64; kk += 2){
                float2 wa = *reinterpret_cast<const float2*>(Wm + kk*64 + 2*lane);
                float2 wb = *reinterpret_cast<const float2*>(Wm + (kk+1)*64 + 2*lane);
                float2 k0v = *reinterpret_cast<const float2*>(XKb + r0*SR2 + kk);
                float2 k1v = *reinterpret_cast<const float2*>(XKb + r1*SR2 + kk);
                float2 q0v = *reinterpret_cast<const float2*>(XQb + r0*SR2 + kk);
                float2 q1v = *reinterpret_cast<const float2*>(XQb + r1*SR2 + kk);
                ull wau = pk2(wa.x, wa.y), wbu = pk2(wb.x, wb.y);
                z0 = ffma2(dup2(k0v.x), wau, z0); z0 = ffma2(dup2(k0v.y), wbu, z0);
                z1 = ffma2(dup2(k1v.x), wau, z1); z1 = ffma2(dup2(k1v.y), wbu, z1);
                p0 = ffma2(dup2(q0v.x), wau, p0); p0 = ffma2(dup2(q0v.y), wbu, p0);
                p1 = ffma2(dup2(q1v.x), wau, p1); p1 = ffma2(dup2(q1v.y), wbu, p1);
            }
        } else {
            // Attn rows 2u, 2u+1  ->  Cc
            const int u = w - 8;
            const int r0 = 2*u, r1 = r0 + 1;
            const int j = lane & 15, half = lane >> 4;
            const float* xkr = XKb + j*SR2 + half*32;
            const float* xq0 = XQb + r0*SR2 + half*32;
            const float* xq1 = XQb + r1*SR2 + half*32;
            float s0 = 0.f, s1v = 0.f;
            #pragma unroll 8
            for (int t = 0; t < 32; t++){
                float xk = xkr[t];
                s0  = fmaf(xq0[t], xk, s0);
                s1v = fmaf(xq1[t], xk, s1v);
            }
            s0  += __shfl_down_sync(0xffffffffu, s0, 16);
            s1v += __shfl_down_sync(0xffffffffu, s1v, 16);
            if (lane < 16){
                float lrj = lrb[j];
                if (j <= r0) Ccs[r0*17 + j] = gsv[r0] * lrj * (s0 + 1.f);
                if (j <= r1) Ccs[r1*17 + j] = gsv[r1] * lrj * (s1v + 1.f);
            }
        }
        __syncthreads();

        // ================= phase B: grad (warps 0..7) =================
        if (w < 8){
            const int r0 = 2*w, r1 = r0 + 1;
            #pragma unroll
            for (int rr = 0; rr < 2; rr++){
                const int r = rr ? r1 : r0;
                float zx, zy; up2(rr ? z1 : z0, zx, zy);
                float s1r = zx + zy, s2r = zx*zx + zy*zy;
                #pragma unroll
                for (int o = 16; o; o >>= 1){
                    s1r += __shfl_xor_sync(0xffffffffu, s1r, o);
                    s2r += __shfl_xor_sync(0xffffffffu, s2r, o);
                }
                float mu = s1r * (1.0f/64.0f);
                float var = s2r * (1.0f/64.0f) - mu*mu;
                float rstd = rsqrtf(var + EPSf);
                float zhx = (zx - mu) * rstd, zhy = (zy - mu) * rstd;
                float2 xv = *reinterpret_cast<const float2*>(XVb + r*SR2 + 2*lane);
                float2 xk = *reinterpret_cast<const float2*>(XKb + r*SR2 + 2*lane);
                float dyx = fmaf(gv2.x, zhx, be2.x) - (xv.x - xk.x);
                float dyy = fmaf(gv2.y, zhy, be2.y) - (xv.y - xk.y);
                float dzx = dyx * gv2.x, dzy = dyy * gv2.y;
                float m1 = dzx + dzy, m2 = fmaf(dzx, zhx, dzy*zhy);
                #pragma unroll
                for (int o = 16; o; o >>= 1){
                    m1 += __shfl_xor_sync(0xffffffffu, m1, o);
                    m2 += __shfl_xor_sync(0xffffffffu, m2, o);
                }
                m1 *= (1.0f/64.0f); m2 *= (1.0f/64.0f);
                float grx = (dzx - m1 - zhx*m2) * rstd;
                float gry = (dzy - m1 - zhy*m2) * rstd;
                *reinterpret_cast<float2*>(Grs + r*GRS + 2*lane) = make_float2(grx, gry);
            }
        }
        __syncthreads();

        // ================= phase C =================
        if (w < 8){
            // Z_bar + ln_fwd + output
            #pragma unroll
            for (int rr = 0; rr < 2; rr++){
                const int r = 2*w + rr;
                float px, py; up2(rr ? p1 : p0, px, py);
                float ax = px + bb2.x, ay = py + bb2.y;
                for (int j = 0; j <= r; j++){
                    float c = Ccs[r*17 + j];
                    float2 gr = *reinterpret_cast<const float2*>(Grs + j*GRS + 2*lane);
                    ax = fmaf(-c, gr.x, ax);
                    ay = fmaf(-c, gr.y, ay);
                }
                float s1r = ax + ay, s2r = ax*ax + ay*ay;
                #pragma unroll
                for (int o = 16; o; o >>= 1){
                    s1r += __shfl_xor_sync(0xffffffffu, s1r, o);
                    s2r += __shfl_xor_sync(0xffffffffu, s2r, o);
                }
                float mu = s1r * (1.0f/64.0f);
                float var = s2r * (1.0f/64.0f) - mu*mu;
                float rstd = rsqrtf(var + EPSf);
                float2 xq = *reinterpret_cast<const float2*>(XQb + r*SR2 + 2*lane);
                float ox = xq.x + fmaf(gv2.x * (ax - mu), rstd, be2.x);
                float oy = xq.y + fmaf(gv2.y * (ay - mu), rstd, be2.y);
                size_t go = base + (size_t)(n*MBb + r) * Dd;
                *reinterpret_cast<float2*>(g_y + go + 2*lane) = make_float2(ox, oy);
            }
        } else {
            // W update (8 kr rows per warp) + b update (warp 8)
            const int u = w - 8;
            const int kr0 = u * 8;
            const float le = gsv[15];
            ull wacc[8];
            #pragma unroll
            for (int q = 0; q < 8; q++) wacc[q] = 0;
            float bx = 0.f, by = 0.f;
            if (u == 0){
                float2 bb2c = *reinterpret_cast<const float2*>(bbv + 2*lane);
                bx = bb2c.x; by = bb2c.y;
            }
            #pragma unroll
            for (int j = 0; j < 16; j++){
                float2 gr = *reinterpret_cast<const float2*>(Grs + j*GRS + 2*lane);
                ull gru = pk2(gr.x, gr.y);
                float cj = le * lrb[j];
                #pragma unroll
                for (int q = 0; q < 8; q++){
                    float t = cj * XKb[j*SR2 + kr0 + q];
                    wacc[q] = ffma2(dup2(t), gru, wacc[q]);
                }
                if (u == 0){
                    bx = fmaf(-cj, gr.x, bx);
                    by = fmaf(-cj, gr.y, by);
                }
            }
            #pragma unroll
            for (int q = 0; q < 8; q++){
                float wx, wy; up2(wacc[q], wx, wy);
                float2* wp = reinterpret_cast<float2*>(Wm + (kr0+q)*64 + 2*lane);
                float2 wv = *wp;
                wv.x -= wx; wv.y -= wy;
                *wp = wv;
            }
            if (u == 0) *reinterpret_cast<float2*>(bnw + 2*lane) = make_float2(bx, by);
        }
        __syncthreads();
        if (tid < 64) bbv[tid] = bnw[tid];
        // next-iter top __syncthreads covers bbv visibility
    }
}

// ---------------- final layernorm over D, writes fp16 hi/lo splits ----------------
__global__ __launch_bounds__(256)
void postln_split_kernel(const float* __restrict__ yin, const float* __restrict__ gmm,
                         const float* __restrict__ bta)
{
    __shared__ float red[8];
    int row = blockIdx.x, tid = threadIdx.x;
    const float* r = yin + (size_t)row * Dd;
    float vals[8];
    float s = 0.f;
    #pragma unroll
    for (int i = 0; i < 8; i++){ vals[i] = r[tid + 256*i]; s += vals[i]; }
    #pragma unroll
    for (int o = 16; o; o >>= 1) s += __shfl_xor_sync(0xffffffffu, s, o);
    if ((tid & 31) == 0) red[tid >> 5] = s;
    __syncthreads();
    float tot = 0.f;
    #pragma unroll
    for (int i = 0; i < 8; i++) tot += red[i];
    float mu = tot * (1.0f / (float)Dd);
    __syncthreads();
    float vs = 0.f;
    #pragma unroll
    for (int i = 0; i < 8; i++){ float d = vals[i] - mu; vs = fmaf(d, d, vs); }
    #pragma unroll
    for (int o = 16; o; o >>= 1) vs += __shfl_xor_sync(0xffffffffu, vs, o);
    if ((tid & 31) == 0) red[tid >> 5] = vs;
    __syncthreads();
    float vtot = 0.f;
    #pragma unroll
    for (int i = 0; i < 8; i++) vtot += red[i];
    float rstd = rsqrtf(vtot * (1.0f / (float)Dd) + EPSf);
    #pragma unroll
    for (int i = 0; i < 8; i++){
        int c = tid + 256*i;
        float val = fmaf(gmm[c] * (vals[i] - mu), rstd, bta[c]);
        __half hv = __float2half_rn(val);
        g_xh[(size_t)row * Dd + c] = hv;
        g_xl[(size_t)row * Dd + c] = __float2half_rn(val - __half2float(hv));
    }
}

// ---------------- launch ----------------
extern "C" void kernel_launch(void* const* d_in, const int* in_sizes, int n_in,
                              void* d_out, int out_size)
{
    const float* x    = (const float*)d_in[0];
    const float* pf   = (const float*)d_in[1];
    const float* Wq   = (const float*)d_in[2];
    const float* Wk   = (const float*)d_in[3];
    const float* Wv   = (const float*)d_in[4];
    const float* Wo   = (const float*)d_in[5];
    const float* pg   = (const float*)d_in[6];
    const float* pb   = (const float*)d_in[7];
    const float* ilrW = (const float*)d_in[8];
    const float* ilrb = (const float*)d_in[9];
    const float* lgs  = (const float*)d_in[10];
    const float* tg   = (const float*)d_in[11];
    const float* tb   = (const float*)d_in[12];
    const float* W0   = (const float*)d_in[13];
    const float* b0   = (const float*)d_in[14];
    float* outp = (float*)d_out;

    float *qp, *kp, *vp, *yp;
    __half *xh, *xl, *wh, *wl;
    cudaGetSymbolAddress((void**)&qp, g_q);
    cudaGetSymbolAddress((void**)&kp, g_k);
    cudaGetSymbolAddress((void**)&vp, g_v);
    cudaGetSymbolAddress((void**)&yp, g_y);
    cudaGetSymbolAddress((void**)&xh, g_xh);
    cudaGetSymbolAddress((void**)&xl, g_xl);
    cudaGetSymbolAddress((void**)&wh, g_wh);
    cudaGetSymbolAddress((void**)&wl, g_wl);

    cudaFuncSetAttribute(gemm_fp16x3, cudaFuncAttributeMaxDynamicSharedMemorySize, GSMEM);
    cudaFuncSetAttribute(scan_kernel, cudaFuncAttributeMaxDynamicSharedMemorySize, SCAN_SMEM_BYTES);

    const int M = Bb * Ss;               // 4096
    const int nw4 = (Dd * Dd) / 4;
    const int nx4 = (M * Dd) / 4;

    split_kernel<<<(nx4 + 255)/256, 256>>>(x,  xh, xl, nx4);
    split_kernel<<<(nw4 + 255)/256, 256>>>(Wq, wh + 0*(size_t)Dd*Dd, wl + 0*(size_t)Dd*Dd, nw4);
    split_kernel<<<(nw4 + 255)/256, 256>>>(Wk, wh + 1*(size_t)Dd*Dd, wl + 1*(size_t)Dd*Dd, nw4);
    split_kernel<<<(nw4 + 255)/256, 256>>>(Wv, wh + 2*(size_t)Dd*Dd, wl + 2*(size_t)Dd*Dd, nw4);

    dim3 ggrid(Dd / BNt, M / BMt, 3);
    gemm_fp16x3<<<ggrid, 256, GSMEM>>>(xh, xl, wh, wl, qp, kp, vp);

    const int rope_total = Bb * Ss * Hh * (HDd/2);
    rope_kernel<<<(rope_total + 255) / 256, 256>>>(pf);

    lr_kernel<<<M, 256>>>(x, ilrW, ilrb);

    scan_kernel<<<Bb * Hh, 512, SCAN_SMEM_BYTES>>>(lgs, tg, tb, W0, b0);

    postln_split_kernel<<<M, 256>>>(yp, pg, pb);

    split_kernel<<<(nw4 + 255)/256, 256>>>(Wo, wh, wl, nw4);
    dim3 ogrid(Dd / BNt, M / BMt, 1);
    gemm_fp16x3<<<ogrid, 256, GSMEM>>>(xh, xl, wh, wl, outp, outp, outp);
}

// round 6
// speedup vs baseline: 2.3025x; 1.0624x over previous
#include <cuda_runtime.h>
#include <cuda_fp16.h>
#include <cstdint>
#include <cstdio>

#define Bb   2
#define Ss   2048
#define Dd   2048
#define Hh   32
#define HDd  64
#define MBb  16
#define Nsteps 128
#define EPSf 1e-5f

typedef unsigned long long ull;

// ---------------- scratch (static device arrays; no allocation) ----------------
__device__ float  g_q[Bb*Ss*Dd];
__device__ float  g_k[Bb*Ss*Dd];
__device__ float  g_v[Bb*Ss*Dd];
__device__ float  g_y[Bb*Ss*Dd];
__device__ float  g_lr[Bb*Hh*Ss];     // h-major: [(b*Hh+h)*Ss + s]
__device__ __half g_xh[Bb*Ss*Dd];
__device__ __half g_xl[Bb*Ss*Dd];
__device__ __half g_wh[3*Dd*Dd];
__device__ __half g_wl[3*Dd*Dd];

// ---------------- PTX helpers ----------------
__device__ __forceinline__ uint32_t smem_u32(const void* p){
    uint32_t a;
    asm("{ .reg .u64 t; cvta.to.shared.u64 t, %1; cvt.u32.u64 %0, t; }" : "=r"(a) : "l"(p));
    return a;
}
__device__ __forceinline__ void cpasync16(uint32_t s, const void* g){
    asm volatile("cp.async.cg.shared.global [%0], [%1], 16;" :: "r"(s), "l"(g) : "memory");
}
#define CP_COMMIT() asm volatile("cp.async.commit_group;" ::: "memory")
#define CP_WAIT(n)  asm volatile("cp.async.wait_group %0;" :: "n"(n) : "memory")

__device__ __forceinline__ void ldsm4(uint32_t* r, uint32_t a){
    asm volatile("ldmatrix.sync.aligned.m8n8.x4.shared.b16 {%0,%1,%2,%3}, [%4];"
        : "=r"(r[0]), "=r"(r[1]), "=r"(r[2]), "=r"(r[3]) : "r"(a));
}
__device__ __forceinline__ void mma16816(float* d, const uint32_t* a, const uint32_t* b){
    asm volatile("mma.sync.aligned.m16n8k16.row.col.f32.f16.f16.f32 "
        "{%0,%1,%2,%3}, {%4,%5,%6,%7}, {%8,%9}, {%0,%1,%2,%3};"
        : "+f"(d[0]), "+f"(d[1]), "+f"(d[2]), "+f"(d[3])
        : "r"(a[0]), "r"(a[1]), "r"(a[2]), "r"(a[3]), "r"(b[0]), "r"(b[1]));
}
__device__ __forceinline__ ull pk2(float lo, float hi){
    ull r; asm("mov.b64 %0, {%1, %2};" : "=l"(r) : "f"(lo), "f"(hi)); return r;
}
__device__ __forceinline__ ull ffma2(ull a, ull b, ull c){
    ull d; asm("fma.rn.f32x2 %0, %1, %2, %3;" : "=l"(d) : "l"(a), "l"(b), "l"(c)); return d;
}
__device__ __forceinline__ void up2(ull v, float& lo, float& hi){
    asm("mov.b64 {%0, %1}, %2;" : "=f"(lo), "=f"(hi) : "l"(v));
}
__device__ __forceinline__ ull dup2(float x){ return pk2(x, x); }

// ---------------- fp16 hi/lo split kernel ----------------
__global__ __launch_bounds__(256)
void split_kernel(const float* __restrict__ src, __half* __restrict__ hi,
                  __half* __restrict__ lo, int n4)
{
    int i = blockIdx.x * blockDim.x + threadIdx.x;
    if (i >= n4) return;
    float4 v = reinterpret_cast<const float4*>(src)[i];
    __half h0 = __float2half_rn(v.x), h1 = __float2half_rn(v.y);
    __half h2 = __float2half_rn(v.z), h3 = __float2half_rn(v.w);
    __half l0 = __float2half_rn(v.x - __half2float(h0));
    __half l1 = __float2half_rn(v.y - __half2float(h1));
    __half l2 = __float2half_rn(v.z - __half2float(h2));
    __half l3 = __float2half_rn(v.w - __half2float(h3));
    __half2* hp = reinterpret_cast<__half2*>(hi + (size_t)i*4);
    __half2* lp = reinterpret_cast<__half2*>(lo + (size_t)i*4);
    hp[0] = __halves2half2(h0, h1); hp[1] = __halves2half2(h2, h3);
    lp[0] = __halves2half2(l0, l1); lp[1] = __halves2half2(l2, l3);
}

// ---------------- HMMA fp16 3x-split NT GEMM: 256x128 CTA tile ----------------
#define BMt 256
#define BNt 128
#define BKt 32
#define RSB 80
#define ATILE_B (256*RSB)       // 20480 per A matrix (hi or lo)
#define BTILE_B (128*RSB)       // 10240 per B matrix
#define STAGE_B (2*ATILE_B + 2*BTILE_B)   // 61440: Ah | Al | Bh | Bl
#define GSMEM  (3*STAGE_B)      // 184320

__global__ __launch_bounds__(256, 1)
void gemm_fp16x3(const __half* __restrict__ Ah, const __half* __restrict__ Al,
                 const __half* __restrict__ Bh, const __half* __restrict__ Bl,
                 float* __restrict__ C0, float* __restrict__ C1, float* __restrict__ C2)
{
    extern __shared__ char sm[];
    const uint32_t sb0 = smem_u32(sm);
    const int tid = threadIdx.x, lane = tid & 31, wid = tid >> 5;
    const int wm = wid & 3, wn = wid >> 2;          // 4 x 2 warp grid, 64x64 warp tile
    const int z = blockIdx.z;
    const __half* bhp = Bh + (size_t)z * Dd * Dd;
    const __half* blp = Bl + (size_t)z * Dd * Dd;
    float* C = (z == 0) ? C0 : (z == 1) ? C1 : C2;
    const int bm = blockIdx.y * BMt, bn = blockIdx.x * BNt;

    const int lr = tid >> 1;            // 0..127
    const int lc = (tid & 1) * 2;       // 16B-chunk pair select

    auto load_stage = [&](int s, int kt){
        const uint32_t st = sb0 + s * STAGE_B;
        const int kel = kt * BKt + lc * 8;
        // A hi/lo: rows lr and lr+128
        #pragma unroll
        for (int p = 0; p < 2; p++){
            const int r = lr + p * 128;
            const __half* gh = Ah + (size_t)(bm + r) * Dd + kel;
            const __half* gl = Al + (size_t)(bm + r) * Dd + kel;
            const uint32_t sa = st + r * RSB + lc * 16;
            cpasync16(sa,              gh);  cpasync16(sa + 16,              gh + 8);
            cpasync16(sa + ATILE_B,    gl);  cpasync16(sa + ATILE_B + 16,    gl + 8);
        }
        // B hi/lo: row lr
        {
            const __half* gh = bhp + (size_t)(bn + lr) * Dd + kel;
            const __half* gl = blp + (size_t)(bn + lr) * Dd + kel;
            const uint32_t sa = st + 2*ATILE_B + lr * RSB + lc * 16;
            cpasync16(sa,              gh);  cpasync16(sa + 16,              gh + 8);
            cpasync16(sa + BTILE_B,    gl);  cpasync16(sa + BTILE_B + 16,    gl + 8);
        }
    };

    float acc[4][8][4];
    #pragma unroll
    for (int i = 0; i < 4; i++)
        #pragma unroll
        for (int j = 0; j < 8; j++)
            #pragma unroll
            for (int u = 0; u < 4; u++) acc[i][j][u] = 0.f;

    const int arow_l = (lane & 15);
    const int acol   = (lane >> 4) * 16;
    const int brow_l = (lane & 7) + ((lane & 16) >> 1);
    const int bcol   = ((lane >> 3) & 1) * 16;

    auto compute_stage = [&](int s){
        const uint32_t st = sb0 + s * STAGE_B;
        #pragma unroll
        for (int ks = 0; ks < 2; ks++){
            const int kb = ks * 32;
            uint32_t ah[4][4], al4[4][4], bh4[4][4], bl4[4][4];
            #pragma unroll
            for (int mt = 0; mt < 4; mt++){
                const uint32_t ra = st + (wm*64 + mt*16 + arow_l) * RSB + kb + acol;
                ldsm4(ah[mt],  ra);
                ldsm4(al4[mt], ra + ATILE_B);
            }
            #pragma unroll
            for (int nb = 0; nb < 4; nb++){
                const uint32_t rb = st + 2*ATILE_B + (wn*64 + nb*16 + brow_l) * RSB + kb + bcol;
                ldsm4(bh4[nb], rb);
                ldsm4(bl4[nb], rb + BTILE_B);
            }
            #pragma unroll
            for (int mt = 0; mt < 4; mt++){
                #pragma unroll
                for (int nt = 0; nt < 8; nt++){
                    const int nb = nt >> 1, pr = (nt & 1) * 2;
                    uint32_t bfh[2] = { bh4[nb][pr], bh4[nb][pr+1] };
                    uint32_t bfl[2] = { bl4[nb][pr], bl4[nb][pr+1] };
                    mma16816(acc[mt][nt], ah[mt],  bfh);
                    mma16816(acc[mt][nt], al4[mt], bfh);
                    mma16816(acc[mt][nt], ah[mt],  bfl);
                }
            }
        }
    };

    const int niter = Dd / BKt;   // 64
    load_stage(0, 0); CP_COMMIT();
    load_stage(1, 1); CP_COMMIT();
    for (int kt = 0; kt < niter; kt++){
        CP_WAIT(1);
        __syncthreads();
        if (kt + 2 < niter){ load_stage((kt + 2) % 3, kt + 2); CP_COMMIT(); }
        else               { CP_COMMIT(); }
        compute_stage(kt % 3);
    }

    #pragma unroll
    for (int mt = 0; mt < 4; mt++){
        const int m = bm + wm*64 + mt*16 + (lane >> 2);
        #pragma unroll
        for (int nt = 0; nt < 8; nt++){
            const int n = bn + wn*64 + nt*8 + 2*(lane & 3);
            *reinterpret_cast<float2*>(C + (size_t)m * Dd + n) =
                make_float2(acc[mt][nt][0], acc[mt][nt][1]);
            *reinterpret_cast<float2*>(C + (size_t)(m + 8) * Dd + n) =
                make_float2(acc[mt][nt][2], acc[mt][nt][3]);
        }
    }
}

// ---------------- RoPE in place on q,k,v ----------------
__global__ void rope_kernel(const float* __restrict__ pf)
{
    int idx = blockIdx.x * blockDim.x + threadIdx.x;
    const int total = Bb * Ss * Hh * (HDd/2);
    if (idx >= total) return;
    int p   = idx & 31;
    int h   = (idx >> 5) & 31;
    int tok = idx >> 10;
    int s   = tok & (Ss - 1);
    float f = pf[s*32 + p];
    float sn, c;
    sincosf(f, &sn, &c);
    size_t off = (size_t)tok * Dd + h * HDd + 2 * p;
    float2* q2 = reinterpret_cast<float2*>(g_q + off);
    float2* k2 = reinterpret_cast<float2*>(g_k + off);
    float2* v2 = reinterpret_cast<float2*>(g_v + off);
    float2 a;
    a = *q2; *q2 = make_float2(a.x*c - a.y*sn, a.x*sn + a.y*c);
    a = *k2; *k2 = make_float2(a.x*c - a.y*sn, a.x*sn + a.y*c);
    a = *v2; *v2 = make_float2(a.x*c - a.y*sn, a.x*sn + a.y*c);
}

// ---------------- learning-rate scalars (h-major output) ----------------
__global__ __launch_bounds__(256)
void lr_kernel(const float* __restrict__ x, const float* __restrict__ ilrW,
               const float* __restrict__ ilrb)
{
    __shared__ float xs[Dd];
    int row = blockIdx.x;
    for (int i = threadIdx.x; i < Dd; i += 256) xs[i] = x[(size_t)row * Dd + i];
    __syncthreads();
    int w = threadIdx.x >> 5, lane = threadIdx.x & 31;
    int b = row >> 11, s = row & (Ss - 1);
    for (int h = w; h < Hh; h += 8){
        const float* wr = ilrW + (size_t)h * Dd;
        float sum = 0.f;
        for (int m = lane; m < Dd; m += 32) sum = fmaf(xs[m], wr[m], sum);
        #pragma unroll
        for (int o = 16; o; o >>= 1) sum += __shfl_xor_sync(0xffffffffu, sum, o);
        if (lane == 0){
            float t = sum + ilrb[h];
            g_lr[((size_t)b * Hh + h) * Ss + s] =
                (1.0f / (1.0f + expf(-t))) * (1.0f / (float)HDd);
        }
    }
}

// ---------------- sequential TTT scan v2: warp-specialized ----------------
#define SR2 68
#define TILEF (16*SR2)
#define GRS 66
#define SCAN_SMEM_FLOATS (3*2*TILEF + 4096 + 16*GRS + 4*64 + 16*17 + 32 + 16)
#define SCAN_SMEM_BYTES  (SCAN_SMEM_FLOATS*4)

__global__ __launch_bounds__(512, 1)
void scan_kernel(const float* __restrict__ lgs, const float* __restrict__ tg,
                 const float* __restrict__ tb,  const float* __restrict__ W0,
                 const float* __restrict__ b0)
{
    extern __shared__ float sms[];
    float* XQs = sms;
    float* XKs = XQs + 2*TILEF;
    float* XVs = XKs + 2*TILEF;
    float* Wm  = XVs + 2*TILEF;
    float* Grs = Wm + 4096;
    float* bbv = Grs + 16*GRS;
    float* bnw = bbv + 64;
    float* gvv = bnw + 64;
    float* bev = gvv + 64;
    float* Ccs = bev + 64;
    float* lrs = Ccs + 16*17;
    float* gsv = lrs + 32;

    const int bh = blockIdx.x;
    const int b = bh >> 5, h = bh & 31;
    const int tid = threadIdx.x, w = tid >> 5, lane = tid & 31;

    for (int i = tid; i < 4096; i += 512) Wm[i] = W0[h*4096 + i];
    if (tid < 64){ bbv[tid] = b0[h*64 + tid]; gvv[tid] = tg[h*64 + tid]; bev[tid] = tb[h*64 + tid]; }
    if (tid < 16) gsv[tid] = fmaxf(1.0f / (float)(tid + 1) + lgs[tid], 0.0f);

    const size_t base = (size_t)b * Ss * Dd + h * HDd;
    const float* lrg = g_lr + ((size_t)b * Hh + h) * Ss;

    const uint32_t sXQ = smem_u32(XQs), sXK = smem_u32(XKs), sXV = smem_u32(XVs);
    const uint32_t sLR = smem_u32(lrs);

    auto prefetch = [&](int n){
        const int bs = n & 1;
        #pragma unroll
        for (int pass = 0; pass < 2; pass++){
            int idx = tid + pass * 512;
            if (idx >= 768) break;
            int tile = idx >> 8;
            int r = (idx >> 4) & 15;
            int c = idx & 15;
            const float* gp = (tile == 0 ? g_q : tile == 1 ? g_k : g_v)
                              + base + (size_t)(n*MBb + r) * Dd + c*4;
            uint32_t sa = (tile == 0 ? sXQ : tile == 1 ? sXK : sXV)
                          + (bs*TILEF + r*SR2 + c*4) * 4;
            cpasync16(sa, gp);
        }
        if (tid < 4) cpasync16(sLR + (bs*16 + tid*4)*4, lrg + n*MBb + tid*4);
    };

    prefetch(0); CP_COMMIT();

    ull z0 = 0, z1 = 0, p0 = 0, p1 = 0;
    float2 bb2 = make_float2(0.f, 0.f), gv2 = make_float2(0.f, 0.f), be2 = make_float2(0.f, 0.f);

    for (int n = 0; n < Nsteps; n++){
        CP_WAIT(0);
        __syncthreads();
        const int bs = n & 1;
        if (n + 1 < Nsteps) prefetch(n + 1);
        CP_COMMIT();

        const float* XQb = XQs + bs*TILEF;
        const float* XKb = XKs + bs*TILEF;
        const float* XVb = XVs + bs*TILEF;
        const float* lrb = lrs + bs*16;

        if (w < 8){
            const int r0 = 2*w, r1 = r0 + 1;
            bb2 = *reinterpret_cast<const float2*>(bbv + 2*lane);
            gv2 = *reinterpret_cast<const float2*>(gvv + 2*lane);
            be2 = *reinterpret_cast<const float2*>(bev + 2*lane);
            z0 = pk2(bb2.x, bb2.y); z1 = z0; p0 = 0; p1 = 0;
            #pragma unroll 4
            for (int kk = 0; kk < 64; kk += 2){
                float2 wa = *reinterpret_cast<const float2*>(Wm + kk*64 + 2*lane);
                float2 wb = *reinterpret_cast<const float2*>(Wm + (kk+1)*64 + 2*lane);
                float2 k0v = *reinterpret_cast<const float2*>(XKb + r0*SR2 + kk);
                float2 k1v = *reinterpret_cast<const float2*>(XKb + r1*SR2 + kk);
                float2 q0v = *reinterpret_cast<const float2*>(XQb + r0*SR2 + kk);
                float2 q1v = *reinterpret_cast<const float2*>(XQb + r1*SR2 + kk);
                ull wau = pk2(wa.x, wa.y), wbu = pk2(wb.x, wb.y);
                z0 = ffma2(dup2(k0v.x), wau, z0); z0 = ffma2(dup2(k0v.y), wbu, z0);
                z1 = ffma2(dup2(k1v.x), wau, z1); z1 = ffma2(dup2(k1v.y), wbu, z1);
                p0 = ffma2(dup2(q0v.x), wau, p0); p0 = ffma2(dup2(q0v.y), wbu, p0);
                p1 = ffma2(dup2(q1v.x), wau, p1); p1 = ffma2(dup2(q1v.y), wbu, p1);
            }
        } else {
            const int u = w - 8;
            const int r0 = 2*u, r1 = r0 + 1;
            const int j = lane & 15, half = lane >> 4;
            const float* xkr = XKb + j*SR2 + half*32;
            const float* xq0 = XQb + r0*SR2 + half*32;
            const float* xq1 = XQb + r1*SR2 + half*32;
            float s0 = 0.f, s1v = 0.f;
            #pragma unroll 8
            for (int t = 0; t < 32; t++){
                float xk = xkr[t];
                s0  = fmaf(xq0[t], xk, s0);
                s1v = fmaf(xq1[t], xk, s1v);
            }
            s0  += __shfl_down_sync(0xffffffffu, s0, 16);
            s1v += __shfl_down_sync(0xffffffffu, s1v, 16);
            if (lane < 16){
                float lrj = lrb[j];
                if (j <= r0) Ccs[r0*17 + j] = gsv[r0] * lrj * (s0 + 1.f);
                if (j <= r1) Ccs[r1*17 + j] = gsv[r1] * lrj * (s1v + 1.f);
            }
        }
        __syncthreads();

        if (w < 8){
            const int r0 = 2*w, r1 = r0 + 1;
            #pragma unroll
            for (int rr = 0; rr < 2; rr++){
                const int r = rr ? r1 : r0;
                float zx, zy; up2(rr ? z1 : z0, zx, zy);
                float s1r = zx + zy, s2r = zx*zx + zy*zy;
                #pragma unroll
                for (int o = 16; o; o >>= 1){
                    s1r += __shfl_xor_sync(0xffffffffu, s1r, o);
                    s2r += __shfl_xor_sync(0xffffffffu, s2r, o);
                }
                float mu = s1r * (1.0f/64.0f);
                float var = s2r * (1.0f/64.0f) - mu*mu;
                float rstd = rsqrtf(var + EPSf);
                float zhx = (zx - mu) * rstd, zhy = (zy - mu) * rstd;
                float2 xv = *reinterpret_cast<const float2*>(XVb + r*SR2 + 2*lane);
                float2 xk = *reinterpret_cast<const float2*>(XKb + r*SR2 + 2*lane);
                float dyx = fmaf(gv2.x, zhx, be2.x) - (xv.x - xk.x);
                float dyy = fmaf(gv2.y, zhy, be2.y) - (xv.y - xk.y);
                float dzx = dyx * gv2.x, dzy = dyy * gv2.y;
                float m1 = dzx + dzy, m2 = fmaf(dzx, zhx, dzy*zhy);
                #pragma unroll
                for (int o = 16; o; o >>= 1){
                    m1 += __shfl_xor_sync(0xffffffffu, m1, o);
                    m2 += __shfl_xor_sync(0xffffffffu, m2, o);
                }
                m1 *= (1.0f/64.0f); m2 *= (1.0f/64.0f);
                float grx = (dzx - m1 - zhx*m2) * rstd;
                float gry = (dzy - m1 - zhy*m2) * rstd;
                *reinterpret_cast<float2*>(Grs + r*GRS + 2*lane) = make_float2(grx, gry);
            }
        }
        __syncthreads();

        if (w < 8){
            #pragma unroll
            for (int rr = 0; rr < 2; rr++){
                const int r = 2*w + rr;
                float px, py; up2(rr ? p1 : p0, px, py);
                float ax = px + bb2.x, ay = py + bb2.y;
                for (int j = 0; j <= r; j++){
                    float c = Ccs[r*17 + j];
                    float2 gr = *reinterpret_cast<const float2*>(Grs + j*GRS + 2*lane);
                    ax = fmaf(-c, gr.x, ax);
                    ay = fmaf(-c, gr.y, ay);
                }
                float s1r = ax + ay, s2r = ax*ax + ay*ay;
                #pragma unroll
                for (int o = 16; o; o >>= 1){
                    s1r += __shfl_xor_sync(0xffffffffu, s1r, o);
                    s2r += __shfl_xor_sync(0xffffffffu, s2r, o);
                }
                float mu = s1r * (1.0f/64.0f);
                float var = s2r * (1.0f/64.0f) - mu*mu;
                float rstd = rsqrtf(var + EPSf);
                float2 xq = *reinterpret_cast<const float2*>(XQb + r*SR2 + 2*lane);
                float ox = xq.x + fmaf(gv2.x * (ax - mu), rstd, be2.x);
                float oy = xq.y + fmaf(gv2.y * (ay - mu), rstd, be2.y);
                size_t go = base + (size_t)(n*MBb + r) * Dd;
                *reinterpret_cast<float2*>(g_y + go + 2*lane) = make_float2(ox, oy);
            }
        } else {
            const int u = w - 8;
            const int kr0 = u * 8;
            const float le = gsv[15];
            ull wacc[8];
            #pragma unroll
            for (int q = 0; q < 8; q++) wacc[q] = 0;
            float bx = 0.f, by = 0.f;
            if (u == 0){
                float2 bb2c = *reinterpret_cast<const float2*>(bbv + 2*lane);
                bx = bb2c.x; by = bb2c.y;
            }
            #pragma unroll
            for (int j = 0; j < 16; j++){
                float2 gr = *reinterpret_cast<const float2*>(Grs + j*GRS + 2*lane);
                ull gru = pk2(gr.x, gr.y);
                float cj = le * lrb[j];
                #pragma unroll
                for (int q = 0; q < 8; q++){
                    float t = cj * XKb[j*SR2 + kr0 + q];
                    wacc[q] = ffma2(dup2(t), gru, wacc[q]);
                }
                if (u == 0){
                    bx = fmaf(-cj, gr.x, bx);
                    by = fmaf(-cj, gr.y, by);
                }
            }
            #pragma unroll
            for (int q = 0; q < 8; q++){
                float wx, wy; up2(wacc[q], wx, wy);
                float2* wp = reinterpret_cast<float2*>(Wm + (kr0+q)*64 + 2*lane);
                float2 wv = *wp;
                wv.x -= wx; wv.y -= wy;
                *wp = wv;
            }
            if (u == 0) *reinterpret_cast<float2*>(bnw + 2*lane) = make_float2(bx, by);
        }
        __syncthreads();
        if (tid < 64) bbv[tid] = bnw[tid];
    }
}

// ---------------- final layernorm over D, writes fp16 hi/lo splits ----------------
__global__ __launch_bounds__(256)
void postln_split_kernel(const float* __restrict__ yin, const float* __restrict__ gmm,
                         const float* __restrict__ bta)
{
    __shared__ float red[8];
    int row = blockIdx.x, tid = threadIdx.x;
    const float* r = yin + (size_t)row * Dd;
    float vals[8];
    float s = 0.f;
    #pragma unroll
    for (int i = 0; i < 8; i++){ vals[i] = r[tid + 256*i]; s += vals[i]; }
    #pragma unroll
    for (int o = 16; o; o >>= 1) s += __shfl_xor_sync(0xffffffffu, s, o);
    if ((tid & 31) == 0) red[tid >> 5] = s;
    __syncthreads();
    float tot = 0.f;
    #pragma unroll
    for (int i = 0; i < 8; i++) tot += red[i];
    float mu = tot * (1.0f / (float)Dd);
    __syncthreads();
    float vs = 0.f;
    #pragma unroll
    for (int i = 0; i < 8; i++){ float d = vals[i] - mu; vs = fmaf(d, d, vs); }
    #pragma unroll
    for (int o = 16; o; o >>= 1) vs += __shfl_xor_sync(0xffffffffu, vs, o);
    if ((tid & 31) == 0) red[tid >> 5] = vs;
    __syncthreads();
    float vtot = 0.f;
    #pragma unroll
    for (int i = 0; i < 8; i++) vtot += red[i];
    float rstd = rsqrtf(vtot * (1.0f / (float)Dd) + EPSf);
    #pragma unroll
    for (int i = 0; i < 8; i++){
        int c = tid + 256*i;
        float val = fmaf(gmm[c] * (vals[i] - mu), rstd, bta[c]);
        __half hv = __float2half_rn(val);
        g_xh[(size_t)row * Dd + c] = hv;
        g_xl[(size_t)row * Dd + c] = __float2half_rn(val - __half2float(hv));
    }
}

// ---------------- launch ----------------
extern "C" void kernel_launch(void* const* d_in, const int* in_sizes, int n_in,
                              void* d_out, int out_size)
{
    const float* x    = (const float*)d_in[0];
    const float* pf   = (const float*)d_in[1];
    const float* Wq   = (const float*)d_in[2];
    const float* Wk   = (const float*)d_in[3];
    const float* Wv   = (const float*)d_in[4];
    const float* Wo   = (const float*)d_in[5];
    const float* pg   = (const float*)d_in[6];
    const float* pb   = (const float*)d_in[7];
    const float* ilrW = (const float*)d_in[8];
    const float* ilrb = (const float*)d_in[9];
    const float* lgs  = (const float*)d_in[10];
    const float* tg   = (const float*)d_in[11];
    const float* tb   = (const float*)d_in[12];
    const float* W0   = (const float*)d_in[13];
    const float* b0   = (const float*)d_in[14];
    float* outp = (float*)d_out;

    float *qp, *kp, *vp, *yp;
    __half *xh, *xl, *wh, *wl;
    cudaGetSymbolAddress((void**)&qp, g_q);
    cudaGetSymbolAddress((void**)&kp, g_k);
    cudaGetSymbolAddress((void**)&vp, g_v);
    cudaGetSymbolAddress((void**)&yp, g_y);
    cudaGetSymbolAddress((void**)&xh, g_xh);
    cudaGetSymbolAddress((void**)&xl, g_xl);
    cudaGetSymbolAddress((void**)&wh, g_wh);
    cudaGetSymbolAddress((void**)&wl, g_wl);

    cudaFuncSetAttribute(gemm_fp16x3, cudaFuncAttributeMaxDynamicSharedMemorySize, GSMEM);
    cudaFuncSetAttribute(scan_kernel, cudaFuncAttributeMaxDynamicSharedMemorySize, SCAN_SMEM_BYTES);

    const int M = Bb * Ss;               // 4096
    const int nw4 = (Dd * Dd) / 4;
    const int nx4 = (M * Dd) / 4;

    split_kernel<<<(nx4 + 255)/256, 256>>>(x,  xh, xl, nx4);
    split_kernel<<<(nw4 + 255)/256, 256>>>(Wq, wh + 0*(size_t)Dd*Dd, wl + 0*(size_t)Dd*Dd, nw4);
    split_kernel<<<(nw4 + 255)/256, 256>>>(Wk, wh + 1*(size_t)Dd*Dd, wl + 1*(size_t)Dd*Dd, nw4);
    split_kernel<<<(nw4 + 255)/256, 256>>>(Wv, wh + 2*(size_t)Dd*Dd, wl + 2*(size_t)Dd*Dd, nw4);

    dim3 ggrid(Dd / BNt, M / BMt, 3);    // (16, 16, 3)
    gemm_fp16x3<<<ggrid, 256, GSMEM>>>(xh, xl, wh, wl, qp, kp, vp);

    const int rope_total = Bb * Ss * Hh * (HDd/2);
    rope_kernel<<<(rope_total + 255) / 256, 256>>>(pf);

    lr_kernel<<<M, 256>>>(x, ilrW, ilrb);

    scan_kernel<<<Bb * Hh, 512, SCAN_SMEM_BYTES>>>(lgs, tg, tb, W0, b0);

    postln_split_kernel<<<M, 256>>>(yp, pg, pb);

    split_kernel<<<(nw4 + 255)/256, 256>>>(Wo, wh, wl, nw4);
    dim3 ogrid(Dd / BNt, M / BMt, 1);    // (16, 16, 1)
    gemm_fp16x3<<<ogrid, 256, GSMEM>>>(xh, xl, wh, wl, outp, outp, outp);
}

// round 7
// speedup vs baseline: 2.8065x; 1.2189x over previous
#include <cuda_runtime.h>
#include <cuda_fp16.h>
#include <cstdint>
#include <cstdio>

#define Bb   2
#define Ss   2048
#define Dd   2048
#define Hh   32
#define HDd  64
#define MBb  16
#define Nsteps 128
#define EPSf 1e-5f

typedef unsigned long long ull;

// ---------------- scratch (static device arrays; no allocation) ----------------
__device__ float  g_q[Bb*Ss*Dd];
__device__ float  g_k[Bb*Ss*Dd];
__device__ float  g_v[Bb*Ss*Dd];
__device__ float  g_y[Bb*Ss*Dd];
__device__ float  g_lr[Bb*Hh*Ss];     // h-major: [(b*Hh+h)*Ss + s]
__device__ __half g_xh[Bb*Ss*Dd];
__device__ __half g_xl[Bb*Ss*Dd];
__device__ __half g_wh[3*Dd*Dd];      // hi split of up to 3 weight matrices

// ---------------- PTX helpers ----------------
__device__ __forceinline__ uint32_t smem_u32(const void* p){
    uint32_t a;
    asm("{ .reg .u64 t; cvta.to.shared.u64 t, %1; cvt.u32.u64 %0, t; }" : "=r"(a) : "l"(p));
    return a;
}
__device__ __forceinline__ void cpasync16(uint32_t s, const void* g){
    asm volatile("cp.async.cg.shared.global [%0], [%1], 16;" :: "r"(s), "l"(g) : "memory");
}
#define CP_COMMIT() asm volatile("cp.async.commit_group;" ::: "memory")
#define CP_WAIT(n)  asm volatile("cp.async.wait_group %0;" :: "n"(n) : "memory")

__device__ __forceinline__ void ldsm4(uint32_t* r, uint32_t a){
    asm volatile("ldmatrix.sync.aligned.m8n8.x4.shared.b16 {%0,%1,%2,%3}, [%4];"
        : "=r"(r[0]), "=r"(r[1]), "=r"(r[2]), "=r"(r[3]) : "r"(a));
}
__device__ __forceinline__ void mma16816(float* d, const uint32_t* a, const uint32_t* b){
    asm volatile("mma.sync.aligned.m16n8k16.row.col.f32.f16.f16.f32 "
        "{%0,%1,%2,%3}, {%4,%5,%6,%7}, {%8,%9}, {%0,%1,%2,%3};"
        : "+f"(d[0]), "+f"(d[1]), "+f"(d[2]), "+f"(d[3])
        : "r"(a[0]), "r"(a[1]), "r"(a[2]), "r"(a[3]), "r"(b[0]), "r"(b[1]));
}
__device__ __forceinline__ ull pk2(float lo, float hi){
    ull r; asm("mov.b64 %0, {%1, %2};" : "=l"(r) : "f"(lo), "f"(hi)); return r;
}
__device__ __forceinline__ ull ffma2(ull a, ull b, ull c){
    ull d; asm("fma.rn.f32x2 %0, %1, %2, %3;" : "=l"(d) : "l"(a), "l"(b), "l"(c)); return d;
}
__device__ __forceinline__ void up2(ull v, float& lo, float& hi){
    asm("mov.b64 {%0, %1}, %2;" : "=f"(lo), "=f"(hi) : "l"(v));
}
__device__ __forceinline__ ull dup2(float x){ return pk2(x, x); }

// ---------------- fp16 hi/lo split (for activations) ----------------
__global__ __launch_bounds__(256)
void split_kernel(const float* __restrict__ src, __half* __restrict__ hi,
                  __half* __restrict__ lo, int n4)
{
    int i = blockIdx.x * blockDim.x + threadIdx.x;
    if (i >= n4) return;
    float4 v = reinterpret_cast<const float4*>(src)[i];
    __half h0 = __float2half_rn(v.x), h1 = __float2half_rn(v.y);
    __half h2 = __float2half_rn(v.z), h3 = __float2half_rn(v.w);
    __half l0 = __float2half_rn(v.x - __half2float(h0));
    __half l1 = __float2half_rn(v.y - __half2float(h1));
    __half l2 = __float2half_rn(v.z - __half2float(h2));
    __half l3 = __float2half_rn(v.w - __half2float(h3));
    __half2* hp = reinterpret_cast<__half2*>(hi + (size_t)i*4);
    __half2* lp = reinterpret_cast<__half2*>(lo + (size_t)i*4);
    hp[0] = __halves2half2(h0, h1); hp[1] = __halves2half2(h2, h3);
    lp[0] = __halves2half2(l0, l1); lp[1] = __halves2half2(l2, l3);
}

// ---------------- fp32 -> fp16 (hi only, for weights) ----------------
__global__ __launch_bounds__(256)
void half_kernel(const float* __restrict__ src, __half* __restrict__ hi, int n4)
{
    int i = blockIdx.x * blockDim.x + threadIdx.x;
    if (i >= n4) return;
    float4 v = reinterpret_cast<const float4*>(src)[i];
    __half2* hp = reinterpret_cast<__half2*>(hi + (size_t)i*4);
    hp[0] = __halves2half2(__float2half_rn(v.x), __float2half_rn(v.y));
    hp[1] = __halves2half2(__float2half_rn(v.z), __float2half_rn(v.w));
}

// ---------------- HMMA fp16 2-term NT GEMM: 256x128 CTA tile ----------------
// C[m,n] = sum_k (Ah+Al)[m,k] * Bh[n,k]; error = -sum A*Bl ~ 7e-5 relative.
#define BMt 256
#define BNt 128
#define BKt 32
#define RSB 80
#define ATILE_B (256*RSB)       // 20480 per A matrix (hi or lo)
#define BTILE_B (128*RSB)       // 10240 for Bh
#define STAGE_B (2*ATILE_B + BTILE_B)   // 51200: Ah | Al | Bh
#define GSMEM  (3*STAGE_B)      // 153600

__global__ __launch_bounds__(256, 1)
void gemm_fp16x2(const __half* __restrict__ Ah, const __half* __restrict__ Al,
                 const __half* __restrict__ Bh,
                 float* __restrict__ C0, float* __restrict__ C1, float* __restrict__ C2)
{
    extern __shared__ char sm[];
    const uint32_t sb0 = smem_u32(sm);
    const int tid = threadIdx.x, lane = tid & 31, wid = tid >> 5;
    const int wm = wid & 3, wn = wid >> 2;          // 4 x 2 warp grid, 64x64 warp tile
    const int z = blockIdx.z;
    const __half* bhp = Bh + (size_t)z * Dd * Dd;
    float* C = (z == 0) ? C0 : (z == 1) ? C1 : C2;
    const int bm = blockIdx.y * BMt, bn = blockIdx.x * BNt;

    const int lr = tid >> 1;            // 0..127
    const int lc = (tid & 1) * 2;       // 16B-chunk pair select

    auto load_stage = [&](int s, int kt){
        const uint32_t st = sb0 + s * STAGE_B;
        const int kel = kt * BKt + lc * 8;
        #pragma unroll
        for (int p = 0; p < 2; p++){
            const int r = lr + p * 128;
            const __half* gh = Ah + (size_t)(bm + r) * Dd + kel;
            const __half* gl = Al + (size_t)(bm + r) * Dd + kel;
            const uint32_t sa = st + r * RSB + lc * 16;
            cpasync16(sa,           gh);  cpasync16(sa + 16,           gh + 8);
            cpasync16(sa + ATILE_B, gl);  cpasync16(sa + ATILE_B + 16, gl + 8);
        }
        {
            const __half* gh = bhp + (size_t)(bn + lr) * Dd + kel;
            const uint32_t sa = st + 2*ATILE_B + lr * RSB + lc * 16;
            cpasync16(sa, gh);  cpasync16(sa + 16, gh + 8);
        }
    };

    float acc[4][8][4];
    #pragma unroll
    for (int i = 0; i < 4; i++)
        #pragma unroll
        for (int j = 0; j < 8; j++)
            #pragma unroll
            for (int u = 0; u < 4; u++) acc[i][j][u] = 0.f;

    const int arow_l = (lane & 15);
    const int acol   = (lane >> 4) * 16;
    const int brow_l = (lane & 7) + ((lane & 16) >> 1);
    const int bcol   = ((lane >> 3) & 1) * 16;

    auto compute_stage = [&](int s){
        const uint32_t st = sb0 + s * STAGE_B;
        #pragma unroll
        for (int ks = 0; ks < 2; ks++){
            const int kb = ks * 32;
            uint32_t ah[4][4], al4[4][4], bh4[4][4];
            #pragma unroll
            for (int mt = 0; mt < 4; mt++){
                const uint32_t ra = st + (wm*64 + mt*16 + arow_l) * RSB + kb + acol;
                ldsm4(ah[mt],  ra);
                ldsm4(al4[mt], ra + ATILE_B);
            }
            #pragma unroll
            for (int nb = 0; nb < 4; nb++){
                const uint32_t rb = st + 2*ATILE_B + (wn*64 + nb*16 + brow_l) * RSB + kb + bcol;
                ldsm4(bh4[nb], rb);
            }
            #pragma unroll
            for (int mt = 0; mt < 4; mt++){
                #pragma unroll
                for (int nt = 0; nt < 8; nt++){
                    const int nb = nt >> 1, pr = (nt & 1) * 2;
                    uint32_t bfh[2] = { bh4[nb][pr], bh4[nb][pr+1] };
                    mma16816(acc[mt][nt], ah[mt],  bfh);
                    mma16816(acc[mt][nt], al4[mt], bfh);
                }
            }
        }
    };

    const int niter = Dd / BKt;   // 64
    load_stage(0, 0); CP_COMMIT();
    load_stage(1, 1); CP_COMMIT();
    for (int kt = 0; kt < niter; kt++){
        CP_WAIT(1);
        __syncthreads();
        if (kt + 2 < niter){ load_stage((kt + 2) % 3, kt + 2); CP_COMMIT(); }
        else               { CP_COMMIT(); }
        compute_stage(kt % 3);
    }

    #pragma unroll
    for (int mt = 0; mt < 4; mt++){
        const int m = bm + wm*64 + mt*16 + (lane >> 2);
        #pragma unroll
        for (int nt = 0; nt < 8; nt++){
            const int n = bn + wn*64 + nt*8 + 2*(lane & 3);
            *reinterpret_cast<float2*>(C + (size_t)m * Dd + n) =
                make_float2(acc[mt][nt][0], acc[mt][nt][1]);
            *reinterpret_cast<float2*>(C + (size_t)(m + 8) * Dd + n) =
                make_float2(acc[mt][nt][2], acc[mt][nt][3]);
        }
    }
}

// ---------------- RoPE in place on q,k,v ----------------
__global__ void rope_kernel(const float* __restrict__ pf)
{
    int idx = blockIdx.x * blockDim.x + threadIdx.x;
    const int total = Bb * Ss * Hh * (HDd/2);
    if (idx >= total) return;
    int p   = idx & 31;
    int h   = (idx >> 5) & 31;
    int tok = idx >> 10;
    int s   = tok & (Ss - 1);
    float f = pf[s*32 + p];
    float sn, c;
    sincosf(f, &sn, &c);
    size_t off = (size_t)tok * Dd + h * HDd + 2 * p;
    float2* q2 = reinterpret_cast<float2*>(g_q + off);
    float2* k2 = reinterpret_cast<float2*>(g_k + off);
    float2* v2 = reinterpret_cast<float2*>(g_v + off);
    float2 a;
    a = *q2; *q2 = make_float2(a.x*c - a.y*sn, a.x*sn + a.y*c);
    a = *k2; *k2 = make_float2(a.x*c - a.y*sn, a.x*sn + a.y*c);
    a = *v2; *v2 = make_float2(a.x*c - a.y*sn, a.x*sn + a.y*c);
}

// ---------------- learning-rate scalars, 8 tokens/block ----------------
#define LRTOK 8
__global__ __launch_bounds__(256)
void lr_kernel(const float* __restrict__ x, const float* __restrict__ ilrW,
               const float* __restrict__ ilrb)
{
    extern __shared__ float xs[];       // LRTOK * Dd
    const int tokb = blockIdx.x * LRTOK;
    for (int i = threadIdx.x; i < LRTOK * Dd; i += 256)
        xs[i] = x[(size_t)tokb * Dd + i];
    __syncthreads();
    const int w = threadIdx.x >> 5, lane = threadIdx.x & 31;
    for (int h = w; h < Hh; h += 8){
        const float* wr = ilrW + (size_t)h * Dd;
        float s[LRTOK];
        #pragma unroll
        for (int t = 0; t < LRTOK; t++) s[t] = 0.f;
        for (int m = lane; m < Dd; m += 32){
            float wv = wr[m];
            #pragma unroll
            for (int t = 0; t < LRTOK; t++) s[t] = fmaf(xs[t*Dd + m], wv, s[t]);
        }
        #pragma unroll
        for (int t = 0; t < LRTOK; t++){
            #pragma unroll
            for (int o = 16; o; o >>= 1) s[t] += __shfl_xor_sync(0xffffffffu, s[t], o);
        }
        if (lane < LRTOK){
            float tval = s[lane] + ilrb[h];
            int tok = tokb + lane;
            int b2 = tok >> 11, s2 = tok & (Ss - 1);
            g_lr[((size_t)b2 * Hh + h) * Ss + s2] =
                (1.0f / (1.0f + expf(-tval))) * (1.0f / (float)HDd);
        }
    }
}

// ---------------- sequential TTT scan: warp-specialized ----------------
#define SR2 68
#define TILEF (16*SR2)
#define GRS 66
#define SCAN_SMEM_FLOATS (3*2*TILEF + 4096 + 16*GRS + 4*64 + 16*17 + 32 + 16)
#define SCAN_SMEM_BYTES  (SCAN_SMEM_FLOATS*4)

__global__ __launch_bounds__(512, 1)
void scan_kernel(const float* __restrict__ lgs, const float* __restrict__ tg,
                 const float* __restrict__ tb,  const float* __restrict__ W0,
                 const float* __restrict__ b0)
{
    extern __shared__ float sms[];
    float* XQs = sms;
    float* XKs = XQs + 2*TILEF;
    float* XVs = XKs + 2*TILEF;
    float* Wm  = XVs + 2*TILEF;
    float* Grs = Wm + 4096;
    float* bbv = Grs + 16*GRS;
    float* bnw = bbv + 64;
    float* gvv = bnw + 64;
    float* bev = gvv + 64;
    float* Ccs = bev + 64;
    float* lrs = Ccs + 16*17;
    float* gsv = lrs + 32;

    const int bh = blockIdx.x;
    const int b = bh >> 5, h = bh & 31;
    const int tid = threadIdx.x, w = tid >> 5, lane = tid & 31;

    for (int i = tid; i < 4096; i += 512) Wm[i] = W0[h*4096 + i];
    if (tid < 64){ bbv[tid] = b0[h*64 + tid]; gvv[tid] = tg[h*64 + tid]; bev[tid] = tb[h*64 + tid]; }
    if (tid < 16) gsv[tid] = fmaxf(1.0f / (float)(tid + 1) + lgs[tid], 0.0f);

    const size_t base = (size_t)b * Ss * Dd + h * HDd;
    const float* lrg = g_lr + ((size_t)b * Hh + h) * Ss;

    const uint32_t sXQ = smem_u32(XQs), sXK = smem_u32(XKs), sXV = smem_u32(XVs);
    const uint32_t sLR = smem_u32(lrs);

    auto prefetch = [&](int n){
        const int bs = n & 1;
        #pragma unroll
        for (int pass = 0; pass < 2; pass++){
            int idx = tid + pass * 512;
            if (idx >= 768) break;
            int tile = idx >> 8;
            int r = (idx >> 4) & 15;
            int c = idx & 15;
            const float* gp = (tile == 0 ? g_q : tile == 1 ? g_k : g_v)
                              + base + (size_t)(n*MBb + r) * Dd + c*4;
            uint32_t sa = (tile == 0 ? sXQ : tile == 1 ? sXK : sXV)
                          + (bs*TILEF + r*SR2 + c*4) * 4;
            cpasync16(sa, gp);
        }
        if (tid < 4) cpasync16(sLR + (bs*16 + tid*4)*4, lrg + n*MBb + tid*4);
    };

    prefetch(0); CP_COMMIT();

    ull z0 = 0, z1 = 0, p0 = 0, p1 = 0;
    float2 bb2 = make_float2(0.f, 0.f), gv2 = make_float2(0.f, 0.f), be2 = make_float2(0.f, 0.f);

    for (int n = 0; n < Nsteps; n++){
        CP_WAIT(0);
        __syncthreads();
        const int bs = n & 1;
        if (n + 1 < Nsteps) prefetch(n + 1);
        CP_COMMIT();

        const float* XQb = XQs + bs*TILEF;
        const float* XKb = XKs + bs*TILEF;
        const float* XVb = XVs + bs*TILEF;
        const float* lrb = lrs + bs*16;

        if (w < 8){
            const int r0 = 2*w, r1 = r0 + 1;
            bb2 = *reinterpret_cast<const float2*>(bbv + 2*lane);
            gv2 = *reinterpret_cast<const float2*>(gvv + 2*lane);
            be2 = *reinterpret_cast<const float2*>(bev + 2*lane);
            z0 = pk2(bb2.x, bb2.y); z1 = z0; p0 = 0; p1 = 0;
            #pragma unroll 4
            for (int kk = 0; kk < 64; kk += 2){
                float2 wa = *reinterpret_cast<const float2*>(Wm + kk*64 + 2*lane);
                float2 wb = *reinterpret_cast<const float2*>(Wm + (kk+1)*64 + 2*lane);
                float2 k0v = *reinterpret_cast<const float2*>(XKb + r0*SR2 + kk);
                float2 k1v = *reinterpret_cast<const float2*>(XKb + r1*SR2 + kk);
                float2 q0v = *reinterpret_cast<const float2*>(XQb + r0*SR2 + kk);
                float2 q1v = *reinterpret_cast<const float2*>(XQb + r1*SR2 + kk);
                ull wau = pk2(wa.x, wa.y), wbu = pk2(wb.x, wb.y);
                z0 = ffma2(dup2(k0v.x), wau, z0); z0 = ffma2(dup2(k0v.y), wbu, z0);
                z1 = ffma2(dup2(k1v.x), wau, z1); z1 = ffma2(dup2(k1v.y), wbu, z1);
                p0 = ffma2(dup2(q0v.x), wau, p0); p0 = ffma2(dup2(q0v.y), wbu, p0);
                p1 = ffma2(dup2(q1v.x), wau, p1); p1 = ffma2(dup2(q1v.y), wbu, p1);
            }
        } else {
            const int u = w - 8;
            const int r0 = 2*u, r1 = r0 + 1;
            const int j = lane & 15, half = lane >> 4;
            const float* xkr = XKb + j*SR2 + half*32;
            const float* xq0 = XQb + r0*SR2 + half*32;
            const float* xq1 = XQb + r1*SR2 + half*32;
            float s0 = 0.f, s1v = 0.f;
            #pragma unroll 8
            for (int t = 0; t < 32; t++){
                float xk = xkr[t];
                s0  = fmaf(xq0[t], xk, s0);
                s1v = fmaf(xq1[t], xk, s1v);
            }
            s0  += __shfl_down_sync(0xffffffffu, s0, 16);
            s1v += __shfl_down_sync(0xffffffffu, s1v, 16);
            if (lane < 16){
                float lrj = lrb[j];
                if (j <= r0) Ccs[r0*17 + j] = gsv[r0] * lrj * (s0 + 1.f);
                if (j <= r1) Ccs[r1*17 + j] = gsv[r1] * lrj * (s1v + 1.f);
            }
        }
        __syncthreads();

        if (w < 8){
            const int r0 = 2*w, r1 = r0 + 1;
            #pragma unroll
            for (int rr = 0; rr < 2; rr++){
                const int r = rr ? r1 : r0;
                float zx, zy; up2(rr ? z1 : z0, zx, zy);
                float s1r = zx + zy, s2r = zx*zx + zy*zy;
                #pragma unroll
                for (int o = 16; o; o >>= 1){
                    s1r += __shfl_xor_sync(0xffffffffu, s1r, o);
                    s2r += __shfl_xor_sync(0xffffffffu, s2r, o);
                }
                float mu = s1r * (1.0f/64.0f);
                float var = s2r * (1.0f/64.0f) - mu*mu;
                float rstd = rsqrtf(var + EPSf);
                float zhx = (zx - mu) * rstd, zhy = (zy - mu) * rstd;
                float2 xv = *reinterpret_cast<const float2*>(XVb + r*SR2 + 2*lane);
                float2 xk = *reinterpret_cast<const float2*>(XKb + r*SR2 + 2*lane);
                float dyx = fmaf(gv2.x, zhx, be2.x) - (xv.x - xk.x);
                float dyy = fmaf(gv2.y, zhy, be2.y) - (xv.y - xk.y);
                float dzx = dyx * gv2.x, dzy = dyy * gv2.y;
                float m1 = dzx + dzy, m2 = fmaf(dzx, zhx, dzy*zhy);
                #pragma unroll
                for (int o = 16; o; o >>= 1){
                    m1 += __shfl_xor_sync(0xffffffffu, m1, o);
                    m2 += __shfl_xor_sync(0xffffffffu, m2, o);
                }
                m1 *= (1.0f/64.0f); m2 *= (1.0f/64.0f);
                float grx = (dzx - m1 - zhx*m2) * rstd;
                float gry = (dzy - m1 - zhy*m2) * rstd;
                *reinterpret_cast<float2*>(Grs + r*GRS + 2*lane) = make_float2(grx, gry);
            }
        }
        __syncthreads();

        if (w < 8){
            #pragma unroll
            for (int rr = 0; rr < 2; rr++){
                const int r = 2*w + rr;
                float px, py; up2(rr ? p1 : p0, px, py);
                float ax = px + bb2.x, ay = py + bb2.y;
                for (int j = 0; j <= r; j++){
                    float c = Ccs[r*17 + j];
                    float2 gr = *reinterpret_cast<const float2*>(Grs + j*GRS + 2*lane);
                    ax = fmaf(-c, gr.x, ax);
                    ay = fmaf(-c, gr.y, ay);
                }
                float s1r = ax + ay, s2r = ax*ax + ay*ay;
                #pragma unroll
                for (int o = 16; o; o >>= 1){
                    s1r += __shfl_xor_sync(0xffffffffu, s1r, o);
                    s2r += __shfl_xor_sync(0xffffffffu, s2r, o);
                }
                float mu = s1r * (1.0f/64.0f);
                float var = s2r * (1.0f/64.0f) - mu*mu;
                float rstd = rsqrtf(var + EPSf);
                float2 xq = *reinterpret_cast<const float2*>(XQb + r*SR2 + 2*lane);
                float ox = xq.x + fmaf(gv2.x * (ax - mu), rstd, be2.x);
                float oy = xq.y + fmaf(gv2.y * (ay - mu), rstd, be2.y);
                size_t go = base + (size_t)(n*MBb + r) * Dd;
                *reinterpret_cast<float2*>(g_y + go + 2*lane) = make_float2(ox, oy);
            }
        } else {
            const int u = w - 8;
            const int kr0 = u * 8;
            const float le = gsv[15];
            ull wacc[8];
            #pragma unroll
            for (int q = 0; q < 8; q++) wacc[q] = 0;
            float bx = 0.f, by = 0.f;
            if (u == 0){
                float2 bb2c = *reinterpret_cast<const float2*>(bbv + 2*lane);
                bx = bb2c.x; by = bb2c.y;
            }
            #pragma unroll
            for (int j = 0; j < 16; j++){
                float2 gr = *reinterpret_cast<const float2*>(Grs + j*GRS + 2*lane);
                ull gru = pk2(gr.x, gr.y);
                float cj = le * lrb[j];
                #pragma unroll
                for (int q = 0; q < 8; q++){
                    float t = cj * XKb[j*SR2 + kr0 + q];
                    wacc[q] = ffma2(dup2(t), gru, wacc[q]);
                }
                if (u == 0){
                    bx = fmaf(-cj, gr.x, bx);
                    by = fmaf(-cj, gr.y, by);
                }
            }
            #pragma unroll
            for (int q = 0; q < 8; q++){
                float wx, wy; up2(wacc[q], wx, wy);
                float2* wp = reinterpret_cast<float2*>(Wm + (kr0+q)*64 + 2*lane);
                float2 wv = *wp;
                wv.x -= wx; wv.y -= wy;
                *wp = wv;
            }
            if (u == 0) *reinterpret_cast<float2*>(bnw + 2*lane) = make_float2(bx, by);
        }
        __syncthreads();
        if (tid < 64) bbv[tid] = bnw[tid];
    }
}

// ---------------- final layernorm over D, writes fp16 hi/lo splits ----------------
__global__ __launch_bounds__(256)
void postln_split_kernel(const float* __restrict__ yin, const float* __restrict__ gmm,
                         const float* __restrict__ bta)
{
    __shared__ float red[8];
    int row = blockIdx.x, tid = threadIdx.x;
    const float* r = yin + (size_t)row * Dd;
    float vals[8];
    float s = 0.f;
    #pragma unroll
    for (int i = 0; i < 8; i++){ vals[i] = r[tid + 256*i]; s += vals[i]; }
    #pragma unroll
    for (int o = 16; o; o >>= 1) s += __shfl_xor_sync(0xffffffffu, s, o);
    if ((tid & 31) == 0) red[tid >> 5] = s;
    __syncthreads();
    float tot = 0.f;
    #pragma unroll
    for (int i = 0; i < 8; i++) tot += red[i];
    float mu = tot * (1.0f / (float)Dd);
    __syncthreads();
    float vs = 0.f;
    #pragma unroll
    for (int i = 0; i < 8; i++){ float d = vals[i] - mu; vs = fmaf(d, d, vs); }
    #pragma unroll
    for (int o = 16; o; o >>= 1) vs += __shfl_xor_sync(0xffffffffu, vs, o);
    if ((tid & 31) == 0) red[tid >> 5] = vs;
    __syncthreads();
    float vtot = 0.f;
    #pragma unroll
    for (int i = 0; i < 8; i++) vtot += red[i];
    float rstd = rsqrtf(vtot * (1.0f / (float)Dd) + EPSf);
    #pragma unroll
    for (int i = 0; i < 8; i++){
        int c = tid + 256*i;
        float val = fmaf(gmm[c] * (vals[i] - mu), rstd, bta[c]);
        __half hv = __float2half_rn(val);
        g_xh[(size_t)row * Dd + c] = hv;
        g_xl[(size_t)row * Dd + c] = __float2half_rn(val - __half2float(hv));
    }
}

// ---------------- launch ----------------
extern "C" void kernel_launch(void* const* d_in, const int* in_sizes, int n_in,
                              void* d_out, int out_size)
{
    const float* x    = (const float*)d_in[0];
    const float* pf   = (const float*)d_in[1];
    const float* Wq   = (const float*)d_in[2];
    const float* Wk   = (const float*)d_in[3];
    const float* Wv   = (const float*)d_in[4];
    const float* Wo   = (const float*)d_in[5];
    const float* pg   = (const float*)d_in[6];
    const float* pb   = (const float*)d_in[7];
    const float* ilrW = (const float*)d_in[8];
    const float* ilrb = (const float*)d_in[9];
    const float* lgs  = (const float*)d_in[10];
    const float* tg   = (const float*)d_in[11];
    const float* tb   = (const float*)d_in[12];
    const float* W0   = (const float*)d_in[13];
    const float* b0   = (const float*)d_in[14];
    float* outp = (float*)d_out;

    float *qp, *kp, *vp, *yp;
    __half *xh, *xl, *wh;
    cudaGetSymbolAddress((void**)&qp, g_q);
    cudaGetSymbolAddress((void**)&kp, g_k);
    cudaGetSymbolAddress((void**)&vp, g_v);
    cudaGetSymbolAddress((void**)&yp, g_y);
    cudaGetSymbolAddress((void**)&xh, g_xh);
    cudaGetSymbolAddress((void**)&xl, g_xl);
    cudaGetSymbolAddress((void**)&wh, g_wh);

    cudaFuncSetAttribute(gemm_fp16x2, cudaFuncAttributeMaxDynamicSharedMemorySize, GSMEM);
    cudaFuncSetAttribute(scan_kernel, cudaFuncAttributeMaxDynamicSharedMemorySize, SCAN_SMEM_BYTES);
    cudaFuncSetAttribute(lr_kernel,   cudaFuncAttributeMaxDynamicSharedMemorySize, LRTOK*Dd*4);

    const int M = Bb * Ss;               // 4096
    const int nw4 = (Dd * Dd) / 4;
    const int nx4 = (M * Dd) / 4;

    split_kernel<<<(nx4 + 255)/256, 256>>>(x,  xh, xl, nx4);
    half_kernel<<<(nw4 + 255)/256, 256>>>(Wq, wh + 0*(size_t)Dd*Dd, nw4);
    half_kernel<<<(nw4 + 255)/256, 256>>>(Wk, wh + 1*(size_t)Dd*Dd, nw4);
    half_kernel<<<(nw4 + 255)/256, 256>>>(Wv, wh + 2*(size_t)Dd*Dd, nw4);

    dim3 ggrid(Dd / BNt, M / BMt, 3);    // (16, 16, 3)
    gemm_fp16x2<<<ggrid, 256, GSMEM>>>(xh, xl, wh, qp, kp, vp);

    const int rope_total = Bb * Ss * Hh * (HDd/2);
    rope_kernel<<<(rope_total + 255) / 256, 256>>>(pf);

    lr_kernel<<<M / LRTOK, 256, LRTOK*Dd*4>>>(x, ilrW, ilrb);

    scan_kernel<<<Bb * Hh, 512, SCAN_SMEM_BYTES>>>(lgs, tg, tb, W0, b0);

    postln_split_kernel<<<M, 256>>>(yp, pg, pb);

    half_kernel<<<(nw4 + 255)/256, 256>>>(Wo, wh, nw4);
    dim3 ogrid(Dd / BNt, M / BMt, 1);    // (16, 16, 1)
    gemm_fp16x2<<<ogrid, 256, GSMEM>>>(xh, xl, wh, outp, outp, outp);
}

// round 8
// speedup vs baseline: 2.8076x; 1.0004x over previous
#include <cuda_runtime.h>
#include <cuda_fp16.h>
#include <cstdint>
#include <cstdio>

#define Bb   2
#define Ss   2048
#define Dd   2048
#define Hh   32
#define HDd  64
#define MBb  16
#define Nsteps 128
#define EPSf 1e-5f

typedef unsigned long long ull;

// ---------------- scratch (static device arrays; no allocation) ----------------
__device__ float  g_q[Bb*Ss*Dd];
__device__ float  g_k[Bb*Ss*Dd];
__device__ float  g_v[Bb*Ss*Dd];
__device__ float  g_y[Bb*Ss*Dd];
__device__ float  g_lr[Bb*Hh*Ss];     // h-major: [(b*Hh+h)*Ss + s]
__device__ __half g_xh[Bb*Ss*Dd];
__device__ __half g_xl[Bb*Ss*Dd];
__device__ __half g_wh[3*Dd*Dd];      // hi split of up to 3 weight matrices

// ---------------- PTX helpers ----------------
__device__ __forceinline__ uint32_t smem_u32(const void* p){
    uint32_t a;
    asm("{ .reg .u64 t; cvta.to.shared.u64 t, %1; cvt.u32.u64 %0, t; }" : "=r"(a) : "l"(p));
    return a;
}
__device__ __forceinline__ void cpasync16(uint32_t s, const void* g){
    asm volatile("cp.async.cg.shared.global [%0], [%1], 16;" :: "r"(s), "l"(g) : "memory");
}
#define CP_COMMIT() asm volatile("cp.async.commit_group;" ::: "memory")
#define CP_WAIT(n)  asm volatile("cp.async.wait_group %0;" :: "n"(n) : "memory")

__device__ __forceinline__ void ldsm4(uint32_t* r, uint32_t a){
    asm volatile("ldmatrix.sync.aligned.m8n8.x4.shared.b16 {%0,%1,%2,%3}, [%4];"
        : "=r"(r[0]), "=r"(r[1]), "=r"(r[2]), "=r"(r[3]) : "r"(a));
}
__device__ __forceinline__ void mma16816(float* d, const uint32_t* a, const uint32_t* b){
    asm volatile("mma.sync.aligned.m16n8k16.row.col.f32.f16.f16.f32 "
        "{%0,%1,%2,%3}, {%4,%5,%6,%7}, {%8,%9}, {%0,%1,%2,%3};"
        : "+f"(d[0]), "+f"(d[1]), "+f"(d[2]), "+f"(d[3])
        : "r"(a[0]), "r"(a[1]), "r"(a[2]), "r"(a[3]), "r"(b[0]), "r"(b[1]));
}
__device__ __forceinline__ ull pk2(float lo, float hi){
    ull r; asm("mov.b64 %0, {%1, %2};" : "=l"(r) : "f"(lo), "f"(hi)); return r;
}
__device__ __forceinline__ ull ffma2(ull a, ull b, ull c){
    ull d; asm("fma.rn.f32x2 %0, %1, %2, %3;" : "=l"(d) : "l"(a), "l"(b), "l"(c)); return d;
}
__device__ __forceinline__ void up2(ull v, float& lo, float& hi){
    asm("mov.b64 {%0, %1}, %2;" : "=f"(lo), "=f"(hi) : "l"(v));
}
__device__ __forceinline__ ull dup2(float x){ return pk2(x, x); }

// ---------------- fp16 hi/lo split (for activations) ----------------
__global__ __launch_bounds__(256)
void split_kernel(const float* __restrict__ src, __half* __restrict__ hi,
                  __half* __restrict__ lo, int n4)
{
    int i = blockIdx.x * blockDim.x + threadIdx.x;
    if (i >= n4) return;
    float4 v = reinterpret_cast<const float4*>(src)[i];
    __half h0 = __float2half_rn(v.x), h1 = __float2half_rn(v.y);
    __half h2 = __float2half_rn(v.z), h3 = __float2half_rn(v.w);
    __half l0 = __float2half_rn(v.x - __half2float(h0));
    __half l1 = __float2half_rn(v.y - __half2float(h1));
    __half l2 = __float2half_rn(v.z - __half2float(h2));
    __half l3 = __float2half_rn(v.w - __half2float(h3));
    __half2* hp = reinterpret_cast<__half2*>(hi + (size_t)i*4);
    __half2* lp = reinterpret_cast<__half2*>(lo + (size_t)i*4);
    hp[0] = __halves2half2(h0, h1); hp[1] = __halves2half2(h2, h3);
    lp[0] = __halves2half2(l0, l1); lp[1] = __halves2half2(l2, l3);
}

// ---------------- fp32 -> fp16 (hi only, for weights) ----------------
__global__ __launch_bounds__(256)
void half_kernel(const float* __restrict__ src, __half* __restrict__ hi, int n4)
{
    int i = blockIdx.x * blockDim.x + threadIdx.x;
    if (i >= n4) return;
    float4 v = reinterpret_cast<const float4*>(src)[i];
    __half2* hp = reinterpret_cast<__half2*>(hi + (size_t)i*4);
    hp[0] = __halves2half2(__float2half_rn(v.x), __float2half_rn(v.y));
    hp[1] = __halves2half2(__float2half_rn(v.z), __float2half_rn(v.w));
}

// ---------------- HMMA fp16 2-term NT GEMM: 256x128 CTA tile ----------------
// C[m,n] = sum_k (Ah+Al)[m,k] * Bh[n,k]; error = -sum A*Bl ~ 7e-5 relative.
#define BMt 256
#define BNt 128
#define BKt 32
#define RSB 80
#define ATILE_B (256*RSB)       // 20480 per A matrix (hi or lo)
#define BTILE_B (128*RSB)       // 10240 for Bh
#define STAGE_B (2*ATILE_B + BTILE_B)   // 51200: Ah | Al | Bh
#define GSMEM  (3*STAGE_B)      // 153600

__global__ __launch_bounds__(256, 1)
void gemm_fp16x2(const __half* __restrict__ Ah, const __half* __restrict__ Al,
                 const __half* __restrict__ Bh,
                 float* __restrict__ C0, float* __restrict__ C1, float* __restrict__ C2)
{
    extern __shared__ char sm[];
    const uint32_t sb0 = smem_u32(sm);
    const int tid = threadIdx.x, lane = tid & 31, wid = tid >> 5;
    const int wm = wid & 3, wn = wid >> 2;          // 4 x 2 warp grid, 64x64 warp tile
    const int z = blockIdx.z;
    const __half* bhp = Bh + (size_t)z * Dd * Dd;
    float* C = (z == 0) ? C0 : (z == 1) ? C1 : C2;
    const int bm = blockIdx.y * BMt, bn = blockIdx.x * BNt;

    const int lr = tid >> 1;            // 0..127
    const int lc = (tid & 1) * 2;       // 16B-chunk pair select

    auto load_stage = [&](int s, int kt){
        const uint32_t st = sb0 + s * STAGE_B;
        const int kel = kt * BKt + lc * 8;
        #pragma unroll
        for (int p = 0; p < 2; p++){
            const int r = lr + p * 128;
            const __half* gh = Ah + (size_t)(bm + r) * Dd + kel;
            const __half* gl = Al + (size_t)(bm + r) * Dd + kel;
            const uint32_t sa = st + r * RSB + lc * 16;
            cpasync16(sa,           gh);  cpasync16(sa + 16,           gh + 8);
            cpasync16(sa + ATILE_B, gl);  cpasync16(sa + ATILE_B + 16, gl + 8);
        }
        {
            const __half* gh = bhp + (size_t)(bn + lr) * Dd + kel;
            const uint32_t sa = st + 2*ATILE_B + lr * RSB + lc * 16;
            cpasync16(sa, gh);  cpasync16(sa + 16, gh + 8);
        }
    };

    float acc[4][8][4];
    #pragma unroll
    for (int i = 0; i < 4; i++)
        #pragma unroll
        for (int j = 0; j < 8; j++)
            #pragma unroll
            for (int u = 0; u < 4; u++) acc[i][j][u] = 0.f;

    const int arow_l = (lane & 15);
    const int acol   = (lane >> 4) * 16;
    const int brow_l = (lane & 7) + ((lane & 16) >> 1);
    const int bcol   = ((lane >> 3) & 1) * 16;

    auto compute_stage = [&](int s){
        const uint32_t st = sb0 + s * STAGE_B;
        #pragma unroll
        for (int ks = 0; ks < 2; ks++){
            const int kb = ks * 32;
            uint32_t ah[4][4], al4[4][4], bh4[4][4];
            #pragma unroll
            for (int mt = 0; mt < 4; mt++){
                const uint32_t ra = st + (wm*64 + mt*16 + arow_l) * RSB + kb + acol;
                ldsm4(ah[mt],  ra);
                ldsm4(al4[mt], ra + ATILE_B);
            }
            #pragma unroll
            for (int nb = 0; nb < 4; nb++){
                const uint32_t rb = st + 2*ATILE_B + (wn*64 + nb*16 + brow_l) * RSB + kb + bcol;
                ldsm4(bh4[nb], rb);
            }
            #pragma unroll
            for (int mt = 0; mt < 4; mt++){
                #pragma unroll
                for (int nt = 0; nt < 8; nt++){
                    const int nb = nt >> 1, pr = (nt & 1) * 2;
                    uint32_t bfh[2] = { bh4[nb][pr], bh4[nb][pr+1] };
                    mma16816(acc[mt][nt], ah[mt],  bfh);
                    mma16816(acc[mt][nt], al4[mt], bfh);
                }
            }
        }
    };

    const int niter = Dd / BKt;   // 64
    load_stage(0, 0); CP_COMMIT();
    load_stage(1, 1); CP_COMMIT();
    for (int kt = 0; kt < niter; kt++){
        CP_WAIT(1);
        __syncthreads();
        if (kt + 2 < niter){ load_stage((kt + 2) % 3, kt + 2); CP_COMMIT(); }
        else               { CP_COMMIT(); }
        compute_stage(kt % 3);
    }

    #pragma unroll
    for (int mt = 0; mt < 4; mt++){
        const int m = bm + wm*64 + mt*16 + (lane >> 2);
        #pragma unroll
        for (int nt = 0; nt < 8; nt++){
            const int n = bn + wn*64 + nt*8 + 2*(lane & 3);
            *reinterpret_cast<float2*>(C + (size_t)m * Dd + n) =
                make_float2(acc[mt][nt][0], acc[mt][nt][1]);
            *reinterpret_cast<float2*>(C + (size_t)(m + 8) * Dd + n) =
                make_float2(acc[mt][nt][2], acc[mt][nt][3]);
        }
    }
}

// ---------------- RoPE in place on q,k,v ----------------
__global__ void rope_kernel(const float* __restrict__ pf)
{
    int idx = blockIdx.x * blockDim.x + threadIdx.x;
    const int total = Bb * Ss * Hh * (HDd/2);
    if (idx >= total) return;
    int p   = idx & 31;
    int h   = (idx >> 5) & 31;
    int tok = idx >> 10;
    int s   = tok & (Ss - 1);
    float f = pf[s*32 + p];
    float sn, c;
    sincosf(f, &sn, &c);
    size_t off = (size_t)tok * Dd + h * HDd + 2 * p;
    float2* q2 = reinterpret_cast<float2*>(g_q + off);
    float2* k2 = reinterpret_cast<float2*>(g_k + off);
    float2* v2 = reinterpret_cast<float2*>(g_v + off);
    float2 a;
    a = *q2; *q2 = make_float2(a.x*c - a.y*sn, a.x*sn + a.y*c);
    a = *k2; *k2 = make_float2(a.x*c - a.y*sn, a.x*sn + a.y*c);
    a = *v2; *v2 = make_float2(a.x*c - a.y*sn, a.x*sn + a.y*c);
}

// ---------------- learning-rate scalars, 8 tokens/block ----------------
#define LRTOK 8
__global__ __launch_bounds__(256)
void lr_kernel(const float* __restrict__ x, const float* __restrict__ ilrW,
               const float* __restrict__ ilrb)
{
    extern __shared__ float xs[];       // LRTOK * Dd
    const int tokb = blockIdx.x * LRTOK;
    for (int i = threadIdx.x; i < LRTOK * Dd; i += 256)
        xs[i] = x[(size_t)tokb * Dd + i];
    __syncthreads();
    const int w = threadIdx.x >> 5, lane = threadIdx.x & 31;
    for (int h = w; h < Hh; h += 8){
        const float* wr = ilrW + (size_t)h * Dd;
        float s[LRTOK];
        #pragma unroll
        for (int t = 0; t < LRTOK; t++) s[t] = 0.f;
        for (int m = lane; m < Dd; m += 32){
            float wv = wr[m];
            #pragma unroll
            for (int t = 0; t < LRTOK; t++) s[t] = fmaf(xs[t*Dd + m], wv, s[t]);
        }
        #pragma unroll
        for (int t = 0; t < LRTOK; t++){
            #pragma unroll
            for (int o = 16; o; o >>= 1) s[t] += __shfl_xor_sync(0xffffffffu, s[t], o);
        }
        if (lane < LRTOK){
            float tval = s[lane] + ilrb[h];
            int tok = tokb + lane;
            int b2 = tok >> 11, s2 = tok & (Ss - 1);
            g_lr[((size_t)b2 * Hh + h) * Ss + s2] =
                (1.0f / (1.0f + expf(-tval))) * (1.0f / (float)HDd);
        }
    }
}

// ---------------- sequential TTT scan: warp-specialized ----------------
#define SR2 68
#define TILEF (16*SR2)
#define GRS 66
#define SCAN_SMEM_FLOATS (3*2*TILEF + 4096 + 16*GRS + 4*64 + 16*17 + 32 + 16)
#define SCAN_SMEM_BYTES  (SCAN_SMEM_FLOATS*4)

__global__ __launch_bounds__(512, 1)
void scan_kernel(const float* __restrict__ lgs, const float* __restrict__ tg,
                 const float* __restrict__ tb,  const float* __restrict__ W0,
                 const float* __restrict__ b0)
{
    extern __shared__ float sms[];
    float* XQs = sms;
    float* XKs = XQs + 2*TILEF;
    float* XVs = XKs + 2*TILEF;
    float* Wm  = XVs + 2*TILEF;
    float* Grs = Wm + 4096;
    float* bbv = Grs + 16*GRS;
    float* bnw = bbv + 64;
    float* gvv = bnw + 64;
    float* bev = gvv + 64;
    float* Ccs = bev + 64;
    float* lrs = Ccs + 16*17;
    float* gsv = lrs + 32;

    const int bh = blockIdx.x;
    const int b = bh >> 5, h = bh & 31;
    const int tid = threadIdx.x, w = tid >> 5, lane = tid & 31;

    for (int i = tid; i < 4096; i += 512) Wm[i] = W0[h*4096 + i];
    if (tid < 64){ bbv[tid] = b0[h*64 + tid]; gvv[tid] = tg[h*64 + tid]; bev[tid] = tb[h*64 + tid]; }
    if (tid < 16) gsv[tid] = fmaxf(1.0f / (float)(tid + 1) + lgs[tid], 0.0f);

    const size_t base = (size_t)b * Ss * Dd + h * HDd;
    const float* lrg = g_lr + ((size_t)b * Hh + h) * Ss;

    const uint32_t sXQ = smem_u32(XQs), sXK = smem_u32(XKs), sXV = smem_u32(XVs);
    const uint32_t sLR = smem_u32(lrs);

    auto prefetch = [&](int n){
        const int bs = n & 1;
        #pragma unroll
        for (int pass = 0; pass < 2; pass++){
            int idx = tid + pass * 512;
            if (idx >= 768) break;
            int tile = idx >> 8;
            int r = (idx >> 4) & 15;
            int c = idx & 15;
            const float* gp = (tile == 0 ? g_q : tile == 1 ? g_k : g_v)
                              + base + (size_t)(n*MBb + r) * Dd + c*4;
            uint32_t sa = (tile == 0 ? sXQ : tile == 1 ? sXK : sXV)
                          + (bs*TILEF + r*SR2 + c*4) * 4;
            cpasync16(sa, gp);
        }
        if (tid < 4) cpasync16(sLR + (bs*16 + tid*4)*4, lrg + n*MBb + tid*4);
    };

    prefetch(0); CP_COMMIT();

    ull z0 = 0, z1 = 0, p0 = 0, p1 = 0;
    float2 bb2 = make_float2(0.f, 0.f), gv2 = make_float2(0.f, 0.f), be2 = make_float2(0.f, 0.f);

    for (int n = 0; n < Nsteps; n++){
        CP_WAIT(0);
        __syncthreads();
        const int bs = n & 1;
        if (n + 1 < Nsteps) prefetch(n + 1);
        CP_COMMIT();

        const float* XQb = XQs + bs*TILEF;
        const float* XKb = XKs + bs*TILEF;
        const float* XVb = XVs + bs*TILEF;
        const float* lrb = lrs + bs*16;

        if (w < 8){
            const int r0 = 2*w, r1 = r0 + 1;
            bb2 = *reinterpret_cast<const float2*>(bbv + 2*lane);
            gv2 = *reinterpret_cast<const float2*>(gvv + 2*lane);
            be2 = *reinterpret_cast<const float2*>(bev + 2*lane);
            z0 = pk2(bb2.x, bb2.y); z1 = z0; p0 = 0; p1 = 0;
            #pragma unroll 4
            for (int kk = 0; kk < 64; kk += 2){
                float2 wa = *reinterpret_cast<const float2*>(Wm + kk*64 + 2*lane);
                float2 wb = *reinterpret_cast<const float2*>(Wm + (kk+1)*64 + 2*lane);
                float2 k0v = *reinterpret_cast<const float2*>(XKb + r0*SR2 + kk);
                float2 k1v = *reinterpret_cast<const float2*>(XKb + r1*SR2 + kk);
                float2 q0v = *reinterpret_cast<const float2*>(XQb + r0*SR2 + kk);
                float2 q1v = *reinterpret_cast<const float2*>(XQb + r1*SR2 + kk);
                ull wau = pk2(wa.x, wa.y), wbu = pk2(wb.x, wb.y);
                z0 = ffma2(dup2(k0v.x), wau, z0); z0 = ffma2(dup2(k0v.y), wbu, z0);
                z1 = ffma2(dup2(k1v.x), wau, z1); z1 = ffma2(dup2(k1v.y), wbu, z1);
                p0 = ffma2(dup2(q0v.x), wau, p0); p0 = ffma2(dup2(q0v.y), wbu, p0);
                p1 = ffma2(dup2(q1v.x), wau, p1); p1 = ffma2(dup2(q1v.y), wbu, p1);
            }
        } else {
            const int u = w - 8;
            const int r0 = 2*u, r1 = r0 + 1;
            const int j = lane & 15, half = lane >> 4;
            const float* xkr = XKb + j*SR2 + half*32;
            const float* xq0 = XQb + r0*SR2 + half*32;
            const float* xq1 = XQb + r1*SR2 + half*32;
            float s0 = 0.f, s1v = 0.f;
            #pragma unroll 8
            for (int t = 0; t < 32; t++){
                float xk = xkr[t];
                s0  = fmaf(xq0[t], xk, s0);
                s1v = fmaf(xq1[t], xk, s1v);
            }
            s0  += __shfl_down_sync(0xffffffffu, s0, 16);
            s1v += __shfl_down_sync(0xffffffffu, s1v, 16);
            if (lane < 16){
                float lrj = lrb[j];
                if (j <= r0) Ccs[r0*17 + j] = gsv[r0] * lrj * (s0 + 1.f);
                if (j <= r1) Ccs[r1*17 + j] = gsv[r1] * lrj * (s1v + 1.f);
            }
        }
        __syncthreads();

        if (w < 8){
            const int r0 = 2*w, r1 = r0 + 1;
            #pragma unroll
            for (int rr = 0; rr < 2; rr++){
                const int r = rr ? r1 : r0;
                float zx, zy; up2(rr ? z1 : z0, zx, zy);
                float s1r = zx + zy, s2r = zx*zx + zy*zy;
                #pragma unroll
                for (int o = 16; o; o >>= 1){
                    s1r += __shfl_xor_sync(0xffffffffu, s1r, o);
                    s2r += __shfl_xor_sync(0xffffffffu, s2r, o);
                }
                float mu = s1r * (1.0f/64.0f);
                float var = s2r * (1.0f/64.0f) - mu*mu;
                float rstd = rsqrtf(var + EPSf);
                float zhx = (zx - mu) * rstd, zhy = (zy - mu) * rstd;
                float2 xv = *reinterpret_cast<const float2*>(XVb + r*SR2 + 2*lane);
                float2 xk = *reinterpret_cast<const float2*>(XKb + r*SR2 + 2*lane);
                float dyx = fmaf(gv2.x, zhx, be2.x) - (xv.x - xk.x);
                float dyy = fmaf(gv2.y, zhy, be2.y) - (xv.y - xk.y);
                float dzx = dyx * gv2.x, dzy = dyy * gv2.y;
                float m1 = dzx + dzy, m2 = fmaf(dzx, zhx, dzy*zhy);
                #pragma unroll
                for (int o = 16; o; o >>= 1){
                    m1 += __shfl_xor_sync(0xffffffffu, m1, o);
                    m2 += __shfl_xor_sync(0xffffffffu, m2, o);
                }
                m1 *= (1.0f/64.0f); m2 *= (1.0f/64.0f);
                float grx = (dzx - m1 - zhx*m2) * rstd;
                float gry = (dzy - m1 - zhy*m2) * rstd;
                *reinterpret_cast<float2*>(Grs + r*GRS + 2*lane) = make_float2(grx, gry);
            }
        }
        __syncthreads();

        if (w < 8){
            #pragma unroll
            for (int rr = 0; rr < 2; rr++){
                const int r = 2*w + rr;
                float px, py; up2(rr ? p1 : p0, px, py);
                float ax = px + bb2.x, ay = py + bb2.y;
                for (int j = 0; j <= r; j++){
                    float c = Ccs[r*17 + j];
                    float2 gr = *reinterpret_cast<const float2*>(Grs + j*GRS + 2*lane);
                    ax = fmaf(-c, gr.x, ax);
                    ay = fmaf(-c, gr.y, ay);
                }
                float s1r = ax + ay, s2r = ax*ax + ay*ay;
                #pragma unroll
                for (int o = 16; o; o >>= 1){
                    s1r += __shfl_xor_sync(0xffffffffu, s1r, o);
                    s2r += __shfl_xor_sync(0xffffffffu, s2r, o);
                }
                float mu = s1r * (1.0f/64.0f);
                float var = s2r * (1.0f/64.0f) - mu*mu;
                float rstd = rsqrtf(var + EPSf);
                float2 xq = *reinterpret_cast<const float2*>(XQb + r*SR2 + 2*lane);
                float ox = xq.x + fmaf(gv2.x * (ax - mu), rstd, be2.x);
                float oy = xq.y + fmaf(gv2.y * (ay - mu), rstd, be2.y);
                size_t go = base + (size_t)(n*MBb + r) * Dd;
                *reinterpret_cast<float2*>(g_y + go + 2*lane) = make_float2(ox, oy);
            }
        } else {
            const int u = w - 8;
            const int kr0 = u * 8;
            const float le = gsv[15];
            ull wacc[8];
            #pragma unroll
            for (int q = 0; q < 8; q++) wacc[q] = 0;
            float bx = 0.f, by = 0.f;
            if (u == 0){
                float2 bb2c = *reinterpret_cast<const float2*>(bbv + 2*lane);
                bx = bb2c.x; by = bb2c.y;
            }
            #pragma unroll
            for (int j = 0; j < 16; j++){
                float2 gr = *reinterpret_cast<const float2*>(Grs + j*GRS + 2*lane);
                ull gru = pk2(gr.x, gr.y);
                float cj = le * lrb[j];
                #pragma unroll
                for (int q = 0; q < 8; q++){
                    float t = cj * XKb[j*SR2 + kr0 + q];
                    wacc[q] = ffma2(dup2(t), gru, wacc[q]);
                }
                if (u == 0){
                    bx = fmaf(-cj, gr.x, bx);
                    by = fmaf(-cj, gr.y, by);
                }
            }
            #pragma unroll
            for (int q = 0; q < 8; q++){
                float wx, wy; up2(wacc[q], wx, wy);
                float2* wp = reinterpret_cast<float2*>(Wm + (kr0+q)*64 + 2*lane);
                float2 wv = *wp;
                wv.x -= wx; wv.y -= wy;
                *wp = wv;
            }
            if (u == 0) *reinterpret_cast<float2*>(bnw + 2*lane) = make_float2(bx, by);
        }
        __syncthreads();
        if (tid < 64) bbv[tid] = bnw[tid];
    }
}

// ---------------- final layernorm over D, writes fp16 hi/lo splits ----------------
__global__ __launch_bounds__(256)
void postln_split_kernel(const float* __restrict__ yin, const float* __restrict__ gmm,
                         const float* __restrict__ bta)
{
    __shared__ float red[8];
    int row = blockIdx.x, tid = threadIdx.x;
    const float* r = yin + (size_t)row * Dd;
    float vals[8];
    float s = 0.f;
    #pragma unroll
    for (int i = 0; i < 8; i++){ vals[i] = r[tid + 256*i]; s += vals[i]; }
    #pragma unroll
    for (int o = 16; o; o >>= 1) s += __shfl_xor_sync(0xffffffffu, s, o);
    if ((tid & 31) == 0) red[tid >> 5] = s;
    __syncthreads();
    float tot = 0.f;
    #pragma unroll
    for (int i = 0; i < 8; i++) tot += red[i];
    float mu = tot * (1.0f / (float)Dd);
    __syncthreads();
    float vs = 0.f;
    #pragma unroll
    for (int i = 0; i < 8; i++){ float d = vals[i] - mu; vs = fmaf(d, d, vs); }
    #pragma unroll
    for (int o = 16; o; o >>= 1) vs += __shfl_xor_sync(0xffffffffu, vs, o);
    if ((tid & 31) == 0) red[tid >> 5] = vs;
    __syncthreads();
    float vtot = 0.f;
    #pragma unroll
    for (int i = 0; i < 8; i++) vtot += red[i];
    float rstd = rsqrtf(vtot * (1.0f / (float)Dd) + EPSf);
    #pragma unroll
    for (int i = 0; i < 8; i++){
        int c = tid + 256*i;
        float val = fmaf(gmm[c] * (vals[i] - mu), rstd, bta[c]);
        __half hv = __float2half_rn(val);
        g_xh[(size_t)row * Dd + c] = hv;
        g_xl[(size_t)row * Dd + c] = __float2half_rn(val - __half2float(hv));
    }
}

// ---------------- launch ----------------
extern "C" void kernel_launch(void* const* d_in, const int* in_sizes, int n_in,
                              void* d_out, int out_size)
{
    const float* x    = (const float*)d_in[0];
    const float* pf   = (const float*)d_in[1];
    const float* Wq   = (const float*)d_in[2];
    const float* Wk   = (const float*)d_in[3];
    const float* Wv   = (const float*)d_in[4];
    const float* Wo   = (const float*)d_in[5];
    const float* pg   = (const float*)d_in[6];
    const float* pb   = (const float*)d_in[7];
    const float* ilrW = (const float*)d_in[8];
    const float* ilrb = (const float*)d_in[9];
    const float* lgs  = (const float*)d_in[10];
    const float* tg   = (const float*)d_in[11];
    const float* tb   = (const float*)d_in[12];
    const float* W0   = (const float*)d_in[13];
    const float* b0   = (const float*)d_in[14];
    float* outp = (float*)d_out;

    float *qp, *kp, *vp, *yp;
    __half *xh, *xl, *wh;
    cudaGetSymbolAddress((void**)&qp, g_q);
    cudaGetSymbolAddress((void**)&kp, g_k);
    cudaGetSymbolAddress((void**)&vp, g_v);
    cudaGetSymbolAddress((void**)&yp, g_y);
    cudaGetSymbolAddress((void**)&xh, g_xh);
    cudaGetSymbolAddress((void**)&xl, g_xl);
    cudaGetSymbolAddress((void**)&wh, g_wh);

    cudaFuncSetAttribute(gemm_fp16x2, cudaFuncAttributeMaxDynamicSharedMemorySize, GSMEM);
    cudaFuncSetAttribute(scan_kernel, cudaFuncAttributeMaxDynamicSharedMemorySize, SCAN_SMEM_BYTES);
    cudaFuncSetAttribute(lr_kernel,   cudaFuncAttributeMaxDynamicSharedMemorySize, LRTOK*Dd*4);

    const int M = Bb * Ss;               // 4096
    const int nw4 = (Dd * Dd) / 4;
    const int nx4 = (M * Dd) / 4;

    split_kernel<<<(nx4 + 255)/256, 256>>>(x,  xh, xl, nx4);
    half_kernel<<<(nw4 + 255)/256, 256>>>(Wq, wh + 0*(size_t)Dd*Dd, nw4);
    half_kernel<<<(nw4 + 255)/256, 256>>>(Wk, wh + 1*(size_t)Dd*Dd, nw4);
    half_kernel<<<(nw4 + 255)/256, 256>>>(Wv, wh + 2*(size_t)Dd*Dd, nw4);

    dim3 ggrid(Dd / BNt, M / BMt, 3);    // (16, 16, 3)
    gemm_fp16x2<<<ggrid, 256, GSMEM>>>(xh, xl, wh, qp, kp, vp);

    const int rope_total = Bb * Ss * Hh * (HDd/2);
    rope_kernel<<<(rope_total + 255) / 256, 256>>>(pf);

    lr_kernel<<<M / LRTOK, 256, LRTOK*Dd*4>>>(x, ilrW, ilrb);

    scan_kernel<<<Bb * Hh, 512, SCAN_SMEM_BYTES>>>(lgs, tg, tb, W0, b0);

    postln_split_kernel<<<M, 256>>>(yp, pg, pb);

    half_kernel<<<(nw4 + 255)/256, 256>>>(Wo, wh, nw4);
    dim3 ogrid(Dd / BNt, M / BMt, 1);    // (16, 16, 1)
    gemm_fp16x2<<<ogrid, 256, GSMEM>>>(xh, xl, wh, outp, outp, outp);
}